// round 14
// baseline (speedup 1.0000x reference)
#include <cuda_runtime.h>
#include <cuda_bf16.h>
#include <math.h>

// Problem constants
#define BB 2
#define EE 1024
#define SS 2048
#define HH 16
#define DD 64
#define BES (BB*EE*SS)          // 4,194,304 elements

// ---------------------------------------------------------------------------
// Scratch (device globals; no runtime allocation allowed)
// ---------------------------------------------------------------------------
__device__ float g_ql[BES], g_kl[BES], g_vl[BES];
__device__ float g_qr[BES], g_kr[BES], g_vr[BES];
__device__ float g_al[BES], g_ar[BES];
__device__ float g_lnout[BES];
__device__ float g_h1[2 * BES];
__device__ float g_wf[2 * EE * EE];
__device__ float g_lam;

// ---------------------------------------------------------------------------
// bf16 split helpers
// ---------------------------------------------------------------------------
__device__ __forceinline__ unsigned bf2pack(float x, float y) {
    __nv_bfloat162 h = __floats2bfloat162_rn(x, y);
    return *reinterpret_cast<unsigned*>(&h);
}
__device__ __forceinline__ float bfhi(float x) {
    return __bfloat162float(__float2bfloat16(x));
}
__device__ __forceinline__ void mma_bf16(
    float& c0, float& c1, float& c2, float& c3,
    unsigned a0, unsigned a1, unsigned a2, unsigned a3,
    unsigned b0, unsigned b1)
{
    asm("mma.sync.aligned.m16n8k16.row.col.f32.bf16.bf16.f32 "
        "{%0,%1,%2,%3}, {%4,%5,%6,%7}, {%8,%9}, {%0,%1,%2,%3};"
        : "+f"(c0), "+f"(c1), "+f"(c2), "+f"(c3)
        : "r"(a0), "r"(a1), "r"(a2), "r"(a3), "r"(b0), "r"(b1));
}

// coalesced 16B cp.async (global -> SMEM)
__device__ __forceinline__ void cpa16(unsigned saddr, const void* gptr) {
    asm volatile("cp.async.cg.shared.global [%0], [%1], 16;"
                 :: "r"(saddr), "l"(gptr));
}

// exp2 via FMA-pipe polynomial (degree-5, rel ~2e-6) — dodges MUFU ceiling.
__device__ __forceinline__ float exp2p(float z) {
    z = fmaxf(z, -100.f);
    float n = rintf(z);
    float f = z - n;
    float p = 0.00133335581f;
    p = fmaf(p, f, 0.00961812911f);
    p = fmaf(p, f, 0.05550410866f);
    p = fmaf(p, f, 0.24022650696f);
    p = fmaf(p, f, 0.69314718056f);
    p = fmaf(p, f, 1.0f);
    float sc = __int_as_float(((int)n + 127) << 23);
    return p * sc;
}

// ---------------------------------------------------------------------------
// Tensor-core GEMM body (3-product split-bf16 m16n8k16), double-buffered,
// two-pass compute (round-8 verified; measured best).
// Per-buffer word layout: Ah[0..1023] Al[1024..2047] Bh[2048..3071] Bl[3072..4095]
// ---------------------------------------------------------------------------
#define GEMM_SMEM (2 * 4096 * 4)

__device__ __forceinline__ void gemm_body(
    const float* __restrict__ W, const float* __restrict__ Xb,
    float* __restrict__ Cb, int bm, int bn,
    int M, int K, int N, const float* __restrict__ bias, float alpha, int relu,
    unsigned* smp)
{
    const int t = threadIdx.x;
    const int lane = t & 31, wid = t >> 5;
    const int warpM = wid >> 2, warpN = wid & 3;

    float acc[4][4][4];
#pragma unroll
    for (int a = 0; a < 4; ++a)
#pragma unroll
        for (int b = 0; b < 4; ++b)
#pragma unroll
            for (int c = 0; c < 4; ++c) acc[a][b][c] = 0.f;

    const int amt = t >> 5, als = t & 31;
    const int amo = (amt << 4) + (als >> 2);
    const int ako = (als & 3) << 1;
    int bno[2], bko[2];
#pragma unroll
    for (int i = 0; i < 2; ++i) {
        int s = t + (i << 8), nt = s >> 5, ls = s & 31;
        bno[i] = (nt << 3) + (ls >> 2);
        bko[i] = (ls & 3) << 1;
    }

    float2 pa[4];
    float2 pb[2][2];

    auto loadG = [&](int k0) {
        const float* ap = W + (size_t)(bm + amo) * K + (k0 + ako);
        pa[0] = *(const float2*)ap;
        pa[1] = *(const float2*)(ap + (size_t)8 * K);
        pa[2] = *(const float2*)(ap + 8);
        pa[3] = *(const float2*)(ap + (size_t)8 * K + 8);
#pragma unroll
        for (int i = 0; i < 2; ++i) {
            const float* bp = Xb + (size_t)(k0 + bko[i]) * N + bn + bno[i];
            pb[i][0] = make_float2(bp[0], bp[N]);
            pb[i][1] = make_float2(bp[(size_t)8 * N], bp[(size_t)9 * N]);
        }
    };

    auto storeS = [&](int buf) {
        unsigned* Ah = smp + buf * 4096;
        unsigned* Al = smp + buf * 4096 + 1024;
        unsigned* Bh = smp + buf * 4096 + 2048;
        unsigned* Bl = smp + buf * 4096 + 3072;
        {
            unsigned h[4], l[4];
#pragma unroll
            for (int r = 0; r < 4; ++r) {
                float hx = bfhi(pa[r].x), hy = bfhi(pa[r].y);
                h[r] = bf2pack(pa[r].x, pa[r].y);
                l[r] = bf2pack(pa[r].x - hx, pa[r].y - hy);
            }
            *(uint4*)&Ah[t * 4] = make_uint4(h[0], h[1], h[2], h[3]);
            *(uint4*)&Al[t * 4] = make_uint4(l[0], l[1], l[2], l[3]);
        }
#pragma unroll
        for (int i = 0; i < 2; ++i) {
            int s = t + (i << 8);
            float hx = bfhi(pb[i][0].x), hy = bfhi(pb[i][0].y);
            unsigned h0 = bf2pack(pb[i][0].x, pb[i][0].y);
            unsigned l0 = bf2pack(pb[i][0].x - hx, pb[i][0].y - hy);
            hx = bfhi(pb[i][1].x); hy = bfhi(pb[i][1].y);
            unsigned h1 = bf2pack(pb[i][1].x, pb[i][1].y);
            unsigned l1 = bf2pack(pb[i][1].x - hx, pb[i][1].y - hy);
            *(uint2*)&Bh[s * 2] = make_uint2(h0, h1);
            *(uint2*)&Bl[s * 2] = make_uint2(l0, l1);
        }
    };

    auto compute = [&](int buf) {
        const unsigned* Ah = smp + buf * 4096;
        const unsigned* Al = smp + buf * 4096 + 1024;
        const unsigned* Bh = smp + buf * 4096 + 2048;
        const unsigned* Bl = smp + buf * 4096 + 3072;
        uint4 af[4];
#pragma unroll
        for (int mt = 0; mt < 4; ++mt)
            af[mt] = *(const uint4*)&Ah[((warpM * 4 + mt) * 32 + lane) * 4];
#pragma unroll
        for (int nt = 0; nt < 4; ++nt) {
            int idx = (warpN * 4 + nt) * 32 + lane;
            uint2 bh = *(const uint2*)&Bh[idx * 2];
            uint2 bl = *(const uint2*)&Bl[idx * 2];
#pragma unroll
            for (int mt = 0; mt < 4; ++mt) {
                float* c = acc[mt][nt];
                mma_bf16(c[0], c[1], c[2], c[3],
                         af[mt].x, af[mt].y, af[mt].z, af[mt].w, bh.x, bh.y);
                mma_bf16(c[0], c[1], c[2], c[3],
                         af[mt].x, af[mt].y, af[mt].z, af[mt].w, bl.x, bl.y);
            }
        }
#pragma unroll
        for (int mt = 0; mt < 4; ++mt)
            af[mt] = *(const uint4*)&Al[((warpM * 4 + mt) * 32 + lane) * 4];
#pragma unroll
        for (int nt = 0; nt < 4; ++nt) {
            int idx = (warpN * 4 + nt) * 32 + lane;
            uint2 bh = *(const uint2*)&Bh[idx * 2];
#pragma unroll
            for (int mt = 0; mt < 4; ++mt) {
                float* c = acc[mt][nt];
                mma_bf16(c[0], c[1], c[2], c[3],
                         af[mt].x, af[mt].y, af[mt].z, af[mt].w, bh.x, bh.y);
            }
        }
    };

    const int kiters = K >> 4;
    loadG(0);
    storeS(0);
    __syncthreads();
    for (int it = 0; it < kiters; ++it) {
        const int cur = it & 1;
        if (it + 1 < kiters) loadG((it + 1) << 4);
        compute(cur);
        if (it + 1 < kiters) storeS(cur ^ 1);
        __syncthreads();
    }

    const int r = lane >> 2, j = lane & 3;
#pragma unroll
    for (int mt = 0; mt < 4; ++mt) {
        const int m0 = bm + warpM * 64 + mt * 16 + r;
        const float bv0 = bias ? bias[m0] : 0.f;
        const float bv1 = bias ? bias[m0 + 8] : 0.f;
#pragma unroll
        for (int nt = 0; nt < 4; ++nt) {
            const int n = bn + warpN * 32 + nt * 8 + j * 2;
            const float* c = acc[mt][nt];
            float r0 = alpha * c[0] + bv0, r1 = alpha * c[1] + bv0;
            float r2 = alpha * c[2] + bv1, r3 = alpha * c[3] + bv1;
            if (relu) {
                r0 = fmaxf(r0, 0.f); r1 = fmaxf(r1, 0.f);
                r2 = fmaxf(r2, 0.f); r3 = fmaxf(r3, 0.f);
            }
            *(float2*)&Cb[(size_t)m0 * N + n] = make_float2(r0, r1);
            *(float2*)&Cb[(size_t)(m0 + 8) * N + n] = make_float2(r2, r3);
        }
    }
}

__global__ __launch_bounds__(256, 2) void gemm_tc(
    const float* __restrict__ W, const float* __restrict__ X,
    float* __restrict__ C, int M, int K, int N,
    const float* __restrict__ bias, float alpha, int relu)
{
    extern __shared__ __align__(16) unsigned smp[];
    gemm_body(W, X + (size_t)blockIdx.z * K * N, C + (size_t)blockIdx.z * M * N,
              blockIdx.y << 7, blockIdx.x << 7, M, K, N, bias, alpha, relu, smp);
}

// QKV projections (z 0..11) + Wf=W1@Wo (z==12) fused in ONE launch.
__global__ __launch_bounds__(256, 2) void gemm_qkvwf(
    const float* __restrict__ Wq_l, const float* __restrict__ Wk_l,
    const float* __restrict__ Wv_l, const float* __restrict__ Wq_r,
    const float* __restrict__ Wk_r, const float* __restrict__ Wv_r,
    const float* __restrict__ left, const float* __restrict__ right,
    const float* __restrict__ W1, const float* __restrict__ Wo,
    float* __restrict__ wf,
    float* ql, float* kl, float* vl, float* qr, float* kr, float* vr,
    float qscale)
{
    extern __shared__ __align__(16) unsigned smp[];
    const int z = blockIdx.z;
    if (z == 12) {
        int tt = blockIdx.y * 16 + blockIdx.x;   // 0..127
        gemm_body(W1, Wo, wf, (tt >> 3) << 7, (tt & 7) << 7,
                  2 * EE, EE, EE, nullptr, 1.f, 0, smp);
        return;
    }
    const int which = z >> 1, b = z & 1;
    const float* Ws[6] = {Wq_l, Wk_l, Wv_l, Wq_r, Wk_r, Wv_r};
    float*       Cs[6] = {ql, kl, vl, qr, kr, vr};
    const float* X = (which < 3) ? left : right;
    const float alpha = (which == 0 || which == 3) ? qscale : 1.f;
    gemm_body(Ws[which], X + (size_t)b * EE * SS, Cs[which] + (size_t)b * EE * SS,
              blockIdx.y << 7, blockIdx.x << 7, EE, EE, SS, nullptr, alpha, 0, smp);
}

// ---------------------------------------------------------------------------
// Tensor-core flash attention — verified fragments/compute; K/V staged as
// raw fp32 tiles via coalesced 16B cp.async (double-buffered; FULL tile
// coverage: 16 threads per 256B row, 4 row-passes), converted to fragments
// from SMEM instead of global.
//
// SMEM (words): Qh[0..4095] Qlo[4096..8191]
//   frag: Kh 8192 Klo 10240 Vh 12288 Vlo 14336 (2048 each)
//   fp32 stage s at 16384 + s*8704: K rows [64][68], V rows [64][68] (+4352)
// Total 33792 words = 132KB -> 1 block/SM (latency hidden by cp.async).
// ---------------------------------------------------------------------------
#define ATTN_SMEM (33792 * 4)
#define STG0 16384
#define STGW 8704
#define ROWW 68

__global__ __launch_bounds__(256) void attn_mma(
    const float* __restrict__ Qlp, const float* __restrict__ Klp,
    const float* __restrict__ Vlp, float* __restrict__ Olp,
    const float* __restrict__ Qrp, const float* __restrict__ Krp,
    const float* __restrict__ Vrp, float* __restrict__ Orp)
{
    extern __shared__ __align__(16) unsigned smw[];
    unsigned* Qh = smw;            // 4096
    unsigned* Qlo = smw + 4096;    // 4096
    unsigned* Kh = smw + 8192;     // 2048
    unsigned* Klo = smw + 10240;   // 2048
    unsigned* Vh = smw + 12288;    // 2048
    unsigned* Vlo = smw + 14336;   // 2048
    const unsigned sb = (unsigned)__cvta_generic_to_shared(smw);

    const int tid = threadIdx.x;
    const int lane = tid & 31, w = tid >> 5;
    const int path = blockIdx.z >> 1;
    const int bz = blockIdx.z & 1;
    const float* Q = path ? Qrp : Qlp;
    const float* Kg = path ? Krp : Klp;
    const float* V = path ? Vrp : Vlp;
    float* O = path ? Orp : Olp;

    const int qt = (gridDim.x - 1) - blockIdx.x;
    const int q0 = qt << 7;
    const size_t base = ((size_t)bz * EE + (size_t)blockIdx.y * DD) * SS;
    const float* Qp = Q + base;
    const float* Kp = Kg + base;
    const float* Vp = V + base;

    // stage tile t0 into buffer stg: 16 threads cover one 256B row; 4 passes.
    const int srow0 = tid >> 4;           // 0..15
    const int sch = (tid & 15) << 2;      // float offset 0..60
    auto stageKV = [&](int t0, int stg) {
        const unsigned sbase = sb + (STG0 + stg * STGW) * 4;
#pragma unroll
        for (int i = 0; i < 4; ++i) {
            int row = srow0 + (i << 4);
            cpa16(sbase + (row * ROWW + sch) * 4,
                  Kp + (size_t)row * SS + t0 + sch);
            cpa16(sbase + ((4352 + row * ROWW + sch)) * 4,
                  Vp + (size_t)row * SS + t0 + sch);
        }
        asm volatile("cp.async.commit_group;" ::: "memory");
    };

    const int ntile = qt * 2 + 2;
    stageKV(0, 0);

    // ---- Q fragments (once per block, from global fp32; unchanged) ----
#pragma unroll
    for (int i = 0; i < 4; ++i) {
        int s = tid + (i << 8);
        int ls = s & 31, kc = (s >> 5) & 3, wq = s >> 7;
        int qr_ = q0 + (wq << 4) + (ls >> 2);
        int d0 = (kc << 4) + ((ls & 3) << 1);
        const float* p00 = Qp + (size_t)d0 * SS + qr_;
        float f0a = p00[0],              f0b = p00[SS];
        float f1a = p00[8],              f1b = p00[SS + 8];
        float f2a = p00[(size_t)8 * SS], f2b = p00[(size_t)9 * SS];
        float f3a = p00[(size_t)8 * SS + 8], f3b = p00[(size_t)9 * SS + 8];
        unsigned h0 = bf2pack(f0a, f0b), h1 = bf2pack(f1a, f1b);
        unsigned h2 = bf2pack(f2a, f2b), h3 = bf2pack(f3a, f3b);
        unsigned l0 = bf2pack(f0a - bfhi(f0a), f0b - bfhi(f0b));
        unsigned l1 = bf2pack(f1a - bfhi(f1a), f1b - bfhi(f1b));
        unsigned l2 = bf2pack(f2a - bfhi(f2a), f2b - bfhi(f2b));
        unsigned l3 = bf2pack(f3a - bfhi(f3a), f3b - bfhi(f3b));
        *(uint4*)&Qh[s * 4]  = make_uint4(h0, h1, h2, h3);
        *(uint4*)&Qlo[s * 4] = make_uint4(l0, l1, l2, l3);
    }

    float o[8][4];
#pragma unroll
    for (int i = 0; i < 8; ++i)
#pragma unroll
        for (int j = 0; j < 4; ++j) o[i][j] = 0.f;
    float m0 = -1e30f, m1 = -1e30f, l0s = 0.f, l1s = 0.f;

    const int qg = q0 + (w << 4) + (lane >> 2);

    for (int kt = 0; kt < ntile; ++kt) {
        const int t0 = kt << 6;
        const int cur = kt & 1;
        if (kt + 1 < ntile) {
            stageKV((kt + 1) << 6, cur ^ 1);
            asm volatile("cp.async.wait_group 1;" ::: "memory");
        } else {
            asm volatile("cp.async.wait_group 0;" ::: "memory");
        }
        __syncthreads();   // stage[cur] visible; also guards frag-smem reuse

        const float* stK = (const float*)(smw + STG0 + cur * STGW);
        const float* stV = stK + 4352;

        // ---- convert staged fp32 -> fragment smem (identical packing) ----
#pragma unroll
        for (int i = 0; i < 4; ++i) {
            int s = tid + (i << 8);
            int ls = s & 31, kc = (s >> 5) & 3, nt = s >> 7;
            int ttl = (nt << 3) + (ls >> 2);
            int d0 = (kc << 4) + ((ls & 3) << 1);
            const float* p00 = stK + d0 * ROWW + ttl;
            float f0a = p00[0], f0b = p00[ROWW];
            float f1a = p00[8 * ROWW], f1b = p00[9 * ROWW];
            *(uint2*)&Kh[s * 2] = make_uint2(bf2pack(f0a, f0b), bf2pack(f1a, f1b));
            *(uint2*)&Klo[s * 2] = make_uint2(
                bf2pack(f0a - bfhi(f0a), f0b - bfhi(f0b)),
                bf2pack(f1a - bfhi(f1a), f1b - bfhi(f1b)));
        }
#pragma unroll
        for (int i = 0; i < 4; ++i) {
            int s = tid + (i << 8);
            int ls = s & 31, tc = (s >> 5) & 3, ndt = s >> 7;
            int d = (ndt << 3) + (ls >> 2);
            int ttl = (tc << 4) + ((ls & 3) << 1);
            const float* p00 = stV + d * ROWW + ttl;
            float2 v0 = make_float2(p00[0], p00[1]);
            float2 v1 = make_float2(p00[8], p00[9]);
            *(uint2*)&Vh[s * 2] = make_uint2(bf2pack(v0.x, v0.y), bf2pack(v1.x, v1.y));
            *(uint2*)&Vlo[s * 2] = make_uint2(
                bf2pack(v0.x - bfhi(v0.x), v0.y - bfhi(v0.y)),
                bf2pack(v1.x - bfhi(v1.x), v1.y - bfhi(v1.y)));
        }
        __syncthreads();

        float sreg[8][4];
#pragma unroll
        for (int i = 0; i < 8; ++i)
#pragma unroll
            for (int j = 0; j < 4; ++j) sreg[i][j] = 0.f;
#pragma unroll
        for (int kc = 0; kc < 4; ++kc) {
            int ai = ((w * 4 + kc) * 32 + lane);
            uint4 ah = *(const uint4*)&Qh[ai * 4];
            uint4 al = *(const uint4*)&Qlo[ai * 4];
#pragma unroll
            for (int nt = 0; nt < 8; ++nt) {
                int bi = ((nt * 4 + kc) * 32 + lane);
                uint2 bh = *(const uint2*)&Kh[bi * 2];
                uint2 bl = *(const uint2*)&Klo[bi * 2];
                float* c = sreg[nt];
                mma_bf16(c[0], c[1], c[2], c[3], ah.x, ah.y, ah.z, ah.w, bh.x, bh.y);
                mma_bf16(c[0], c[1], c[2], c[3], ah.x, ah.y, ah.z, ah.w, bl.x, bl.y);
                mma_bf16(c[0], c[1], c[2], c[3], al.x, al.y, al.z, al.w, bh.x, bh.y);
            }
        }

        float mx0 = m0, mx1 = m1;
#pragma unroll
        for (int nt = 0; nt < 8; ++nt) {
            int tb = t0 + (nt << 3) + ((lane & 3) << 1);
            if (tb > qg)     sreg[nt][0] = -1e30f;
            if (tb + 1 > qg) sreg[nt][1] = -1e30f;
            if (tb > qg + 8)     sreg[nt][2] = -1e30f;
            if (tb + 1 > qg + 8) sreg[nt][3] = -1e30f;
            mx0 = fmaxf(mx0, fmaxf(sreg[nt][0], sreg[nt][1]));
            mx1 = fmaxf(mx1, fmaxf(sreg[nt][2], sreg[nt][3]));
        }
        mx0 = fmaxf(mx0, __shfl_xor_sync(0xffffffffu, mx0, 1));
        mx0 = fmaxf(mx0, __shfl_xor_sync(0xffffffffu, mx0, 2));
        mx1 = fmaxf(mx1, __shfl_xor_sync(0xffffffffu, mx1, 1));
        mx1 = fmaxf(mx1, __shfl_xor_sync(0xffffffffu, mx1, 2));
        float corr0 = exp2p(m0 - mx0), corr1 = exp2p(m1 - mx1);
        m0 = mx0; m1 = mx1;
        l0s *= corr0; l1s *= corr1;
#pragma unroll
        for (int nt = 0; nt < 8; ++nt) {
            o[nt][0] *= corr0; o[nt][1] *= corr0;
            o[nt][2] *= corr1; o[nt][3] *= corr1;
        }
        float ls0 = 0.f, ls1 = 0.f;
#pragma unroll
        for (int nt = 0; nt < 8; ++nt) {
            float p0 = exp2p(sreg[nt][0] - mx0);
            float p1 = exp2p(sreg[nt][1] - mx0);
            float p2 = exp2p(sreg[nt][2] - mx1);
            float p3 = exp2p(sreg[nt][3] - mx1);
            sreg[nt][0] = p0; sreg[nt][1] = p1;
            sreg[nt][2] = p2; sreg[nt][3] = p3;
            ls0 += p0 + p1; ls1 += p2 + p3;
        }
        ls0 += __shfl_xor_sync(0xffffffffu, ls0, 1);
        ls0 += __shfl_xor_sync(0xffffffffu, ls0, 2);
        ls1 += __shfl_xor_sync(0xffffffffu, ls1, 1);
        ls1 += __shfl_xor_sync(0xffffffffu, ls1, 2);
        l0s += ls0; l1s += ls1;

#pragma unroll
        for (int j = 0; j < 4; ++j) {
            float* pA = sreg[2 * j];
            float* pB = sreg[2 * j + 1];
            unsigned ah0 = bf2pack(pA[0], pA[1]);
            unsigned ah1 = bf2pack(pA[2], pA[3]);
            unsigned ah2 = bf2pack(pB[0], pB[1]);
            unsigned ah3 = bf2pack(pB[2], pB[3]);
            unsigned al0 = bf2pack(pA[0] - bfhi(pA[0]), pA[1] - bfhi(pA[1]));
            unsigned al1 = bf2pack(pA[2] - bfhi(pA[2]), pA[3] - bfhi(pA[3]));
            unsigned al2 = bf2pack(pB[0] - bfhi(pB[0]), pB[1] - bfhi(pB[1]));
            unsigned al3 = bf2pack(pB[2] - bfhi(pB[2]), pB[3] - bfhi(pB[3]));
#pragma unroll
            for (int nt = 0; nt < 8; ++nt) {
                int bi = ((nt * 4 + j) * 32 + lane);
                uint2 bh = *(const uint2*)&Vh[bi * 2];
                uint2 bl = *(const uint2*)&Vlo[bi * 2];
                float* c = o[nt];
                mma_bf16(c[0], c[1], c[2], c[3], ah0, ah1, ah2, ah3, bh.x, bh.y);
                mma_bf16(c[0], c[1], c[2], c[3], ah0, ah1, ah2, ah3, bl.x, bl.y);
                mma_bf16(c[0], c[1], c[2], c[3], al0, al1, al2, al3, bh.x, bh.y);
            }
        }
    }

    const float inv0 = 1.f / l0s, inv1 = 1.f / l1s;
    float* Op = O + base;
#pragma unroll
    for (int nt = 0; nt < 8; ++nt) {
        int d = (nt << 3) + ((lane & 3) << 1);
        Op[(size_t)d * SS + qg]       = o[nt][0] * inv0;
        Op[(size_t)(d + 1) * SS + qg] = o[nt][1] * inv0;
        Op[(size_t)d * SS + qg + 8]       = o[nt][2] * inv1;
        Op[(size_t)(d + 1) * SS + qg + 8] = o[nt][3] * inv1;
    }
}

// ---------------------------------------------------------------------------
// lambda = exp(sum lam_q_l*lam_k_l) - exp(sum lam_q_r*lam_k_r) + 0.1
// ---------------------------------------------------------------------------
__global__ void lam_kernel(const float* __restrict__ ql, const float* __restrict__ kl,
                           const float* __restrict__ qr, const float* __restrict__ kr)
{
    const int t = threadIdx.x;
    float a = ql[t] * kl[t] + ql[t + 32] * kl[t + 32];
    float b = qr[t] * kr[t] + qr[t + 32] * kr[t + 32];
#pragma unroll
    for (int off = 16; off > 0; off >>= 1) {
        a += __shfl_xor_sync(0xffffffffu, a, off);
        b += __shfl_xor_sync(0xffffffffu, b, off);
    }
    if (t == 0) g_lam = expf(a) - expf(b) + 0.1f;
}

// ---------------------------------------------------------------------------
// combined = attn_l - lam*attn_r; LayerNorm over E (biased var, eps 1e-5).
// ---------------------------------------------------------------------------
__global__ __launch_bounds__(512) void ln_kernel(
    const float* __restrict__ al, const float* __restrict__ ar,
    const float* __restrict__ gg, const float* __restrict__ bbv,
    float* __restrict__ out)
{
    __shared__ float ps[16][32], pq[16][32], smu[32], srs[32];
    const int tid = threadIdx.x;
    const int ty = tid >> 5, sl = tid & 31;
    const int b = blockIdx.x >> 6;
    const int s = ((blockIdx.x & 63) << 5) + sl;
    const float lam = g_lam;
    const size_t col = (size_t)b * EE * SS + s;
    const int e0 = ty << 6;

    float sum = 0.f, sq = 0.f;
    for (int e = e0; e < e0 + 64; ++e) {
        size_t idx = col + (size_t)e * SS;
        float c = al[idx] - lam * ar[idx];
        sum += c; sq += c * c;
    }
    ps[ty][sl] = sum; pq[ty][sl] = sq;
    __syncthreads();
    if (ty == 0) {
        float ts = 0.f, tq = 0.f;
#pragma unroll
        for (int r = 0; r < 16; ++r) { ts += ps[r][sl]; tq += pq[r][sl]; }
        float mu = ts * (1.f / EE);
        float var = tq * (1.f / EE) - mu * mu;
        smu[sl] = mu;
        srs[sl] = rsqrtf(var + 1e-5f);
    }
    __syncthreads();
    const float mu = smu[sl], rs = srs[sl];
    for (int e = e0; e < e0 + 64; ++e) {
        size_t idx = col + (size_t)e * SS;
        float c = al[idx] - lam * ar[idx];
        out[idx] = (c - mu) * rs * gg[e] + bbv[e];
    }
}

// ---------------------------------------------------------------------------
// Launch
// ---------------------------------------------------------------------------
static float* sym_addr(const void* symbol)
{
    void* p = nullptr;
    cudaGetSymbolAddress(&p, symbol);
    return (float*)p;
}

extern "C" void kernel_launch(void* const* d_in, const int* in_sizes, int n_in,
                              void* d_out, int out_size)
{
    const float* left  = (const float*)d_in[0];
    const float* right = (const float*)d_in[1];
    const float* Wq_l  = (const float*)d_in[2];
    const float* Wk_l  = (const float*)d_in[3];
    const float* Wv_l  = (const float*)d_in[4];
    const float* Wq_r  = (const float*)d_in[5];
    const float* Wk_r  = (const float*)d_in[6];
    const float* Wv_r  = (const float*)d_in[7];
    const float* Wo    = (const float*)d_in[8];
    const float* lql   = (const float*)d_in[9];
    const float* lkl   = (const float*)d_in[10];
    const float* lqr   = (const float*)d_in[11];
    const float* lkr   = (const float*)d_in[12];
    const float* ln_g  = (const float*)d_in[13];
    const float* ln_b  = (const float*)d_in[14];
    const float* W1    = (const float*)d_in[15];
    const float* b1    = (const float*)d_in[16];
    const float* W2    = (const float*)d_in[17];
    const float* b2    = (const float*)d_in[18];
    float* out = (float*)d_out;

    float* ql = sym_addr(g_ql); float* kl = sym_addr(g_kl); float* vl = sym_addr(g_vl);
    float* qr = sym_addr(g_qr); float* kr = sym_addr(g_kr); float* vr = sym_addr(g_vr);
    float* al = sym_addr(g_al); float* ar = sym_addr(g_ar);
    float* lno = sym_addr(g_lnout);
    float* h1 = sym_addr(g_h1);
    float* wf = sym_addr(g_wf);

    // D^-0.5 * log2(e): scores in log2 domain (softmax-invariant)
    const float qscale = 0.125f * 1.4426950408889634f;

    cudaFuncSetAttribute(gemm_tc, cudaFuncAttributeMaxDynamicSharedMemorySize,
                         GEMM_SMEM);
    cudaFuncSetAttribute(gemm_qkvwf, cudaFuncAttributeMaxDynamicSharedMemorySize,
                         GEMM_SMEM);
    cudaFuncSetAttribute(attn_mma, cudaFuncAttributeMaxDynamicSharedMemorySize,
                         ATTN_SMEM);

    dim3 blk(256);

    // QKV projections + Wf=W1@Wo fused into one launch (z = 0..12)
    gemm_qkvwf<<<dim3(SS / 128, EE / 128, 13), blk, GEMM_SMEM>>>(
        Wq_l, Wk_l, Wv_l, Wq_r, Wk_r, Wv_r, left, right, W1, Wo, wf,
        ql, kl, vl, qr, kr, vr, qscale);

    // attention: both paths in one launch (z = path*2 + b)
    attn_mma<<<dim3(SS / 128, HH, 2 * BB), 256, ATTN_SMEM>>>(
        ql, kl, vl, al, qr, kr, vr, ar);

    // lambda, combine + LN
    lam_kernel<<<1, 32>>>(lql, lkl, lqr, lkr);
    ln_kernel<<<BB * (SS / 32), 512>>>(al, ar, ln_g, ln_b, lno);

    // fused (W1@Wo) + relu, then W2 straight into d_out ([B,E,S])
    gemm_tc<<<dim3(SS / 128, 2 * EE / 128, BB), blk, GEMM_SMEM>>>(
        wf, lno, h1, 2 * EE, EE, SS, b1, 1.f, 1);
    gemm_tc<<<dim3(SS / 128, EE / 128, BB), blk, GEMM_SMEM>>>(
        W2, h1, out, EE, 2 * EE, SS, b2, 1.f, 0);
}

// round 15
// speedup vs baseline: 1.0844x; 1.0844x over previous
#include <cuda_runtime.h>
#include <cuda_bf16.h>
#include <math.h>

// Problem constants
#define BB 2
#define EE 1024
#define SS 2048
#define HH 16
#define DD 64
#define BES (BB*EE*SS)          // 4,194,304 elements

// ---------------------------------------------------------------------------
// Scratch (device globals; no runtime allocation allowed)
// ---------------------------------------------------------------------------
__device__ float g_ql[BES], g_kl[BES], g_vl[BES];
__device__ float g_qr[BES], g_kr[BES], g_vr[BES];
__device__ float g_al[BES], g_ar[BES];
__device__ float g_lnout[BES];
__device__ float g_h1[2 * BES];
__device__ float g_wf[2 * EE * EE];

// ---------------------------------------------------------------------------
// bf16 split helpers
// ---------------------------------------------------------------------------
__device__ __forceinline__ unsigned bf2pack(float x, float y) {
    __nv_bfloat162 h = __floats2bfloat162_rn(x, y);
    return *reinterpret_cast<unsigned*>(&h);
}
__device__ __forceinline__ float bfhi(float x) {
    return __bfloat162float(__float2bfloat16(x));
}
__device__ __forceinline__ void mma_bf16(
    float& c0, float& c1, float& c2, float& c3,
    unsigned a0, unsigned a1, unsigned a2, unsigned a3,
    unsigned b0, unsigned b1)
{
    asm("mma.sync.aligned.m16n8k16.row.col.f32.bf16.bf16.f32 "
        "{%0,%1,%2,%3}, {%4,%5,%6,%7}, {%8,%9}, {%0,%1,%2,%3};"
        : "+f"(c0), "+f"(c1), "+f"(c2), "+f"(c3)
        : "r"(a0), "r"(a1), "r"(a2), "r"(a3), "r"(b0), "r"(b1));
}

// exp2 via FMA-pipe polynomial (degree-5, rel ~2e-6) — dodges MUFU ceiling.
__device__ __forceinline__ float exp2p(float z) {
    z = fmaxf(z, -100.f);
    float n = rintf(z);
    float f = z - n;
    float p = 0.00133335581f;
    p = fmaf(p, f, 0.00961812911f);
    p = fmaf(p, f, 0.05550410866f);
    p = fmaf(p, f, 0.24022650696f);
    p = fmaf(p, f, 0.69314718056f);
    p = fmaf(p, f, 1.0f);
    float sc = __int_as_float(((int)n + 127) << 23);
    return p * sc;
}

// ---------------------------------------------------------------------------
// Tensor-core GEMM body (3-product split-bf16 m16n8k16), double-buffered,
// two-pass compute (round-8/12 verified; measured best).
// Per-buffer word layout: Ah[0..1023] Al[1024..2047] Bh[2048..3071] Bl[3072..4095]
// ---------------------------------------------------------------------------
#define GEMM_SMEM (2 * 4096 * 4)

__device__ __forceinline__ void gemm_body(
    const float* __restrict__ W, const float* __restrict__ Xb,
    float* __restrict__ Cb, int bm, int bn,
    int M, int K, int N, const float* __restrict__ bias, float alpha, int relu,
    unsigned* smp)
{
    const int t = threadIdx.x;
    const int lane = t & 31, wid = t >> 5;
    const int warpM = wid >> 2, warpN = wid & 3;

    float acc[4][4][4];
#pragma unroll
    for (int a = 0; a < 4; ++a)
#pragma unroll
        for (int b = 0; b < 4; ++b)
#pragma unroll
            for (int c = 0; c < 4; ++c) acc[a][b][c] = 0.f;

    const int amt = t >> 5, als = t & 31;
    const int amo = (amt << 4) + (als >> 2);
    const int ako = (als & 3) << 1;
    int bno[2], bko[2];
#pragma unroll
    for (int i = 0; i < 2; ++i) {
        int s = t + (i << 8), nt = s >> 5, ls = s & 31;
        bno[i] = (nt << 3) + (ls >> 2);
        bko[i] = (ls & 3) << 1;
    }

    float2 pa[4];
    float2 pb[2][2];

    auto loadG = [&](int k0) {
        const float* ap = W + (size_t)(bm + amo) * K + (k0 + ako);
        pa[0] = *(const float2*)ap;
        pa[1] = *(const float2*)(ap + (size_t)8 * K);
        pa[2] = *(const float2*)(ap + 8);
        pa[3] = *(const float2*)(ap + (size_t)8 * K + 8);
#pragma unroll
        for (int i = 0; i < 2; ++i) {
            const float* bp = Xb + (size_t)(k0 + bko[i]) * N + bn + bno[i];
            pb[i][0] = make_float2(bp[0], bp[N]);
            pb[i][1] = make_float2(bp[(size_t)8 * N], bp[(size_t)9 * N]);
        }
    };

    auto storeS = [&](int buf) {
        unsigned* Ah = smp + buf * 4096;
        unsigned* Al = smp + buf * 4096 + 1024;
        unsigned* Bh = smp + buf * 4096 + 2048;
        unsigned* Bl = smp + buf * 4096 + 3072;
        {
            unsigned h[4], l[4];
#pragma unroll
            for (int r = 0; r < 4; ++r) {
                float hx = bfhi(pa[r].x), hy = bfhi(pa[r].y);
                h[r] = bf2pack(pa[r].x, pa[r].y);
                l[r] = bf2pack(pa[r].x - hx, pa[r].y - hy);
            }
            *(uint4*)&Ah[t * 4] = make_uint4(h[0], h[1], h[2], h[3]);
            *(uint4*)&Al[t * 4] = make_uint4(l[0], l[1], l[2], l[3]);
        }
#pragma unroll
        for (int i = 0; i < 2; ++i) {
            int s = t + (i << 8);
            float hx = bfhi(pb[i][0].x), hy = bfhi(pb[i][0].y);
            unsigned h0 = bf2pack(pb[i][0].x, pb[i][0].y);
            unsigned l0 = bf2pack(pb[i][0].x - hx, pb[i][0].y - hy);
            hx = bfhi(pb[i][1].x); hy = bfhi(pb[i][1].y);
            unsigned h1 = bf2pack(pb[i][1].x, pb[i][1].y);
            unsigned l1 = bf2pack(pb[i][1].x - hx, pb[i][1].y - hy);
            *(uint2*)&Bh[s * 2] = make_uint2(h0, h1);
            *(uint2*)&Bl[s * 2] = make_uint2(l0, l1);
        }
    };

    auto compute = [&](int buf) {
        const unsigned* Ah = smp + buf * 4096;
        const unsigned* Al = smp + buf * 4096 + 1024;
        const unsigned* Bh = smp + buf * 4096 + 2048;
        const unsigned* Bl = smp + buf * 4096 + 3072;
        uint4 af[4];
#pragma unroll
        for (int mt = 0; mt < 4; ++mt)
            af[mt] = *(const uint4*)&Ah[((warpM * 4 + mt) * 32 + lane) * 4];
#pragma unroll
        for (int nt = 0; nt < 4; ++nt) {
            int idx = (warpN * 4 + nt) * 32 + lane;
            uint2 bh = *(const uint2*)&Bh[idx * 2];
            uint2 bl = *(const uint2*)&Bl[idx * 2];
#pragma unroll
            for (int mt = 0; mt < 4; ++mt) {
                float* c = acc[mt][nt];
                mma_bf16(c[0], c[1], c[2], c[3],
                         af[mt].x, af[mt].y, af[mt].z, af[mt].w, bh.x, bh.y);
                mma_bf16(c[0], c[1], c[2], c[3],
                         af[mt].x, af[mt].y, af[mt].z, af[mt].w, bl.x, bl.y);
            }
        }
#pragma unroll
        for (int mt = 0; mt < 4; ++mt)
            af[mt] = *(const uint4*)&Al[((warpM * 4 + mt) * 32 + lane) * 4];
#pragma unroll
        for (int nt = 0; nt < 4; ++nt) {
            int idx = (warpN * 4 + nt) * 32 + lane;
            uint2 bh = *(const uint2*)&Bh[idx * 2];
#pragma unroll
            for (int mt = 0; mt < 4; ++mt) {
                float* c = acc[mt][nt];
                mma_bf16(c[0], c[1], c[2], c[3],
                         af[mt].x, af[mt].y, af[mt].z, af[mt].w, bh.x, bh.y);
            }
        }
    };

    const int kiters = K >> 4;
    loadG(0);
    storeS(0);
    __syncthreads();
    for (int it = 0; it < kiters; ++it) {
        const int cur = it & 1;
        if (it + 1 < kiters) loadG((it + 1) << 4);
        compute(cur);
        if (it + 1 < kiters) storeS(cur ^ 1);
        __syncthreads();
    }

    const int r = lane >> 2, j = lane & 3;
#pragma unroll
    for (int mt = 0; mt < 4; ++mt) {
        const int m0 = bm + warpM * 64 + mt * 16 + r;
        const float bv0 = bias ? bias[m0] : 0.f;
        const float bv1 = bias ? bias[m0 + 8] : 0.f;
#pragma unroll
        for (int nt = 0; nt < 4; ++nt) {
            const int n = bn + warpN * 32 + nt * 8 + j * 2;
            const float* c = acc[mt][nt];
            float r0 = alpha * c[0] + bv0, r1 = alpha * c[1] + bv0;
            float r2 = alpha * c[2] + bv1, r3 = alpha * c[3] + bv1;
            if (relu) {
                r0 = fmaxf(r0, 0.f); r1 = fmaxf(r1, 0.f);
                r2 = fmaxf(r2, 0.f); r3 = fmaxf(r3, 0.f);
            }
            *(float2*)&Cb[(size_t)m0 * N + n] = make_float2(r0, r1);
            *(float2*)&Cb[(size_t)(m0 + 8) * N + n] = make_float2(r2, r3);
        }
    }
}

__global__ __launch_bounds__(256, 2) void gemm_tc(
    const float* __restrict__ W, const float* __restrict__ X,
    float* __restrict__ C, int M, int K, int N,
    const float* __restrict__ bias, float alpha, int relu)
{
    extern __shared__ __align__(16) unsigned smp[];
    gemm_body(W, X + (size_t)blockIdx.z * K * N, C + (size_t)blockIdx.z * M * N,
              blockIdx.y << 7, blockIdx.x << 7, M, K, N, bias, alpha, relu, smp);
}

// QKV projections (z 0..11) + Wf=W1@Wo (z==12) fused in ONE launch.
__global__ __launch_bounds__(256, 2) void gemm_qkvwf(
    const float* __restrict__ Wq_l, const float* __restrict__ Wk_l,
    const float* __restrict__ Wv_l, const float* __restrict__ Wq_r,
    const float* __restrict__ Wk_r, const float* __restrict__ Wv_r,
    const float* __restrict__ left, const float* __restrict__ right,
    const float* __restrict__ W1, const float* __restrict__ Wo,
    float* __restrict__ wf,
    float* ql, float* kl, float* vl, float* qr, float* kr, float* vr,
    float qscale)
{
    extern __shared__ __align__(16) unsigned smp[];
    const int z = blockIdx.z;
    if (z == 12) {
        int tt = blockIdx.y * 16 + blockIdx.x;   // 0..127
        gemm_body(W1, Wo, wf, (tt >> 3) << 7, (tt & 7) << 7,
                  2 * EE, EE, EE, nullptr, 1.f, 0, smp);
        return;
    }
    const int which = z >> 1, b = z & 1;
    const float* Ws[6] = {Wq_l, Wk_l, Wv_l, Wq_r, Wk_r, Wv_r};
    float*       Cs[6] = {ql, kl, vl, qr, kr, vr};
    const float* X = (which < 3) ? left : right;
    const float alpha = (which == 0 || which == 3) ? qscale : 1.f;
    gemm_body(Ws[which], X + (size_t)b * EE * SS, Cs[which] + (size_t)b * EE * SS,
              blockIdx.y << 7, blockIdx.x << 7, EE, EE, SS, nullptr, alpha, 0, smp);
}

// ---------------------------------------------------------------------------
// Tensor-core flash attention (causal), split-bf16 3-product, FA2 fragment
// chaining, log2-domain softmax via exp2p. (round-8/12 verified, unchanged)
// ---------------------------------------------------------------------------
#define ATTN_SMEM (16384 * 4)

__global__ __launch_bounds__(256, 2) void attn_mma(
    const float* __restrict__ Qlp, const float* __restrict__ Klp,
    const float* __restrict__ Vlp, float* __restrict__ Olp,
    const float* __restrict__ Qrp, const float* __restrict__ Krp,
    const float* __restrict__ Vrp, float* __restrict__ Orp)
{
    extern __shared__ __align__(16) unsigned smw[];
    unsigned* Qh = smw;            // 4096
    unsigned* Qlo = smw + 4096;    // 4096
    unsigned* Kh = smw + 8192;     // 2048
    unsigned* Klo = smw + 10240;   // 2048
    unsigned* Vh = smw + 12288;    // 2048
    unsigned* Vlo = smw + 14336;   // 2048

    const int tid = threadIdx.x;
    const int lane = tid & 31, w = tid >> 5;
    const int path = blockIdx.z >> 1;
    const int bz = blockIdx.z & 1;
    const float* Q = path ? Qrp : Qlp;
    const float* Kg = path ? Krp : Klp;
    const float* V = path ? Vrp : Vlp;
    float* O = path ? Orp : Olp;

    const int qt = (gridDim.x - 1) - blockIdx.x;
    const int q0 = qt << 7;
    const size_t base = ((size_t)bz * EE + (size_t)blockIdx.y * DD) * SS;
    const float* Qp = Q + base;
    const float* Kp = Kg + base;
    const float* Vp = V + base;

#pragma unroll
    for (int i = 0; i < 4; ++i) {
        int s = tid + (i << 8);
        int ls = s & 31, kc = (s >> 5) & 3, wq = s >> 7;
        int qr_ = q0 + (wq << 4) + (ls >> 2);
        int d0 = (kc << 4) + ((ls & 3) << 1);
        const float* p00 = Qp + (size_t)d0 * SS + qr_;
        float f0a = p00[0],              f0b = p00[SS];
        float f1a = p00[8],              f1b = p00[SS + 8];
        float f2a = p00[(size_t)8 * SS], f2b = p00[(size_t)9 * SS];
        float f3a = p00[(size_t)8 * SS + 8], f3b = p00[(size_t)9 * SS + 8];
        unsigned h0 = bf2pack(f0a, f0b), h1 = bf2pack(f1a, f1b);
        unsigned h2 = bf2pack(f2a, f2b), h3 = bf2pack(f3a, f3b);
        unsigned l0 = bf2pack(f0a - bfhi(f0a), f0b - bfhi(f0b));
        unsigned l1 = bf2pack(f1a - bfhi(f1a), f1b - bfhi(f1b));
        unsigned l2 = bf2pack(f2a - bfhi(f2a), f2b - bfhi(f2b));
        unsigned l3 = bf2pack(f3a - bfhi(f3a), f3b - bfhi(f3b));
        *(uint4*)&Qh[s * 4]  = make_uint4(h0, h1, h2, h3);
        *(uint4*)&Qlo[s * 4] = make_uint4(l0, l1, l2, l3);
    }

    float o[8][4];
#pragma unroll
    for (int i = 0; i < 8; ++i)
#pragma unroll
        for (int j = 0; j < 4; ++j) o[i][j] = 0.f;
    float m0 = -1e30f, m1 = -1e30f, l0s = 0.f, l1s = 0.f;

    const int qg = q0 + (w << 4) + (lane >> 2);
    const int ntile = qt * 2 + 2;

    for (int kt = 0; kt < ntile; ++kt) {
        const int t0 = kt << 6;
        __syncthreads();
#pragma unroll
        for (int i = 0; i < 4; ++i) {
            int s = tid + (i << 8);
            int ls = s & 31, kc = (s >> 5) & 3, nt = s >> 7;
            int tt = t0 + (nt << 3) + (ls >> 2);
            int d0 = (kc << 4) + ((ls & 3) << 1);
            const float* p00 = Kp + (size_t)d0 * SS + tt;
            float f0a = p00[0], f0b = p00[SS];
            float f1a = p00[(size_t)8 * SS], f1b = p00[(size_t)9 * SS];
            *(uint2*)&Kh[s * 2] = make_uint2(bf2pack(f0a, f0b), bf2pack(f1a, f1b));
            *(uint2*)&Klo[s * 2] = make_uint2(
                bf2pack(f0a - bfhi(f0a), f0b - bfhi(f0b)),
                bf2pack(f1a - bfhi(f1a), f1b - bfhi(f1b)));
        }
#pragma unroll
        for (int i = 0; i < 4; ++i) {
            int s = tid + (i << 8);
            int ls = s & 31, tc = (s >> 5) & 3, ndt = s >> 7;
            int d = (ndt << 3) + (ls >> 2);
            int tt = t0 + (tc << 4) + ((ls & 3) << 1);
            const float* p00 = Vp + (size_t)d * SS + tt;
            float2 v0 = *(const float2*)p00;
            float2 v1 = *(const float2*)(p00 + 8);
            *(uint2*)&Vh[s * 2] = make_uint2(bf2pack(v0.x, v0.y), bf2pack(v1.x, v1.y));
            *(uint2*)&Vlo[s * 2] = make_uint2(
                bf2pack(v0.x - bfhi(v0.x), v0.y - bfhi(v0.y)),
                bf2pack(v1.x - bfhi(v1.x), v1.y - bfhi(v1.y)));
        }
        __syncthreads();

        float sreg[8][4];
#pragma unroll
        for (int i = 0; i < 8; ++i)
#pragma unroll
            for (int j = 0; j < 4; ++j) sreg[i][j] = 0.f;
#pragma unroll
        for (int kc = 0; kc < 4; ++kc) {
            int ai = ((w * 4 + kc) * 32 + lane);
            uint4 ah = *(const uint4*)&Qh[ai * 4];
            uint4 al = *(const uint4*)&Qlo[ai * 4];
#pragma unroll
            for (int nt = 0; nt < 8; ++nt) {
                int bi = ((nt * 4 + kc) * 32 + lane);
                uint2 bh = *(const uint2*)&Kh[bi * 2];
                uint2 bl = *(const uint2*)&Klo[bi * 2];
                float* c = sreg[nt];
                mma_bf16(c[0], c[1], c[2], c[3], ah.x, ah.y, ah.z, ah.w, bh.x, bh.y);
                mma_bf16(c[0], c[1], c[2], c[3], ah.x, ah.y, ah.z, ah.w, bl.x, bl.y);
                mma_bf16(c[0], c[1], c[2], c[3], al.x, al.y, al.z, al.w, bh.x, bh.y);
            }
        }

        float mx0 = m0, mx1 = m1;
#pragma unroll
        for (int nt = 0; nt < 8; ++nt) {
            int tb = t0 + (nt << 3) + ((lane & 3) << 1);
            if (tb > qg)     sreg[nt][0] = -1e30f;
            if (tb + 1 > qg) sreg[nt][1] = -1e30f;
            if (tb > qg + 8)     sreg[nt][2] = -1e30f;
            if (tb + 1 > qg + 8) sreg[nt][3] = -1e30f;
            mx0 = fmaxf(mx0, fmaxf(sreg[nt][0], sreg[nt][1]));
            mx1 = fmaxf(mx1, fmaxf(sreg[nt][2], sreg[nt][3]));
        }
        mx0 = fmaxf(mx0, __shfl_xor_sync(0xffffffffu, mx0, 1));
        mx0 = fmaxf(mx0, __shfl_xor_sync(0xffffffffu, mx0, 2));
        mx1 = fmaxf(mx1, __shfl_xor_sync(0xffffffffu, mx1, 1));
        mx1 = fmaxf(mx1, __shfl_xor_sync(0xffffffffu, mx1, 2));
        float corr0 = exp2p(m0 - mx0), corr1 = exp2p(m1 - mx1);
        m0 = mx0; m1 = mx1;
        l0s *= corr0; l1s *= corr1;
#pragma unroll
        for (int nt = 0; nt < 8; ++nt) {
            o[nt][0] *= corr0; o[nt][1] *= corr0;
            o[nt][2] *= corr1; o[nt][3] *= corr1;
        }
        float ls0 = 0.f, ls1 = 0.f;
#pragma unroll
        for (int nt = 0; nt < 8; ++nt) {
            float p0 = exp2p(sreg[nt][0] - mx0);
            float p1 = exp2p(sreg[nt][1] - mx0);
            float p2 = exp2p(sreg[nt][2] - mx1);
            float p3 = exp2p(sreg[nt][3] - mx1);
            sreg[nt][0] = p0; sreg[nt][1] = p1;
            sreg[nt][2] = p2; sreg[nt][3] = p3;
            ls0 += p0 + p1; ls1 += p2 + p3;
        }
        ls0 += __shfl_xor_sync(0xffffffffu, ls0, 1);
        ls0 += __shfl_xor_sync(0xffffffffu, ls0, 2);
        ls1 += __shfl_xor_sync(0xffffffffu, ls1, 1);
        ls1 += __shfl_xor_sync(0xffffffffu, ls1, 2);
        l0s += ls0; l1s += ls1;

#pragma unroll
        for (int j = 0; j < 4; ++j) {
            float* pA = sreg[2 * j];
            float* pB = sreg[2 * j + 1];
            unsigned ah0 = bf2pack(pA[0], pA[1]);
            unsigned ah1 = bf2pack(pA[2], pA[3]);
            unsigned ah2 = bf2pack(pB[0], pB[1]);
            unsigned ah3 = bf2pack(pB[2], pB[3]);
            unsigned al0 = bf2pack(pA[0] - bfhi(pA[0]), pA[1] - bfhi(pA[1]));
            unsigned al1 = bf2pack(pA[2] - bfhi(pA[2]), pA[3] - bfhi(pA[3]));
            unsigned al2 = bf2pack(pB[0] - bfhi(pB[0]), pB[1] - bfhi(pB[1]));
            unsigned al3 = bf2pack(pB[2] - bfhi(pB[2]), pB[3] - bfhi(pB[3]));
#pragma unroll
            for (int nt = 0; nt < 8; ++nt) {
                int bi = ((nt * 4 + j) * 32 + lane);
                uint2 bh = *(const uint2*)&Vh[bi * 2];
                uint2 bl = *(const uint2*)&Vlo[bi * 2];
                float* c = o[nt];
                mma_bf16(c[0], c[1], c[2], c[3], ah0, ah1, ah2, ah3, bh.x, bh.y);
                mma_bf16(c[0], c[1], c[2], c[3], ah0, ah1, ah2, ah3, bl.x, bl.y);
                mma_bf16(c[0], c[1], c[2], c[3], al0, al1, al2, al3, bh.x, bh.y);
            }
        }
    }

    const float inv0 = 1.f / l0s, inv1 = 1.f / l1s;
    float* Op = O + base;
#pragma unroll
    for (int nt = 0; nt < 8; ++nt) {
        int d = (nt << 3) + ((lane & 3) << 1);
        Op[(size_t)d * SS + qg]       = o[nt][0] * inv0;
        Op[(size_t)(d + 1) * SS + qg] = o[nt][1] * inv0;
        Op[(size_t)d * SS + qg + 8]       = o[nt][2] * inv1;
        Op[(size_t)(d + 1) * SS + qg + 8] = o[nt][3] * inv1;
    }
}

// ---------------------------------------------------------------------------
// combined = attn_l - lam*attn_r; LayerNorm over E (biased var, eps 1e-5).
// lambda computed inline per block (identical shfl math as before; no extra
// kernel launch). 1024 threads = 32 e-groups x 32 s; grid = B*S/32 = 128.
// ---------------------------------------------------------------------------
__global__ __launch_bounds__(1024) void ln_kernel(
    const float* __restrict__ al, const float* __restrict__ ar,
    const float* __restrict__ gg, const float* __restrict__ bbv,
    const float* __restrict__ lql, const float* __restrict__ lkl,
    const float* __restrict__ lqr, const float* __restrict__ lkr,
    float* __restrict__ out)
{
    __shared__ float ps[32][32], pq[32][32], smu[32], srs[32], slam;
    const int tid = threadIdx.x;
    const int ty = tid >> 5, sl = tid & 31;

    // lambda (warp 0; same math as the old lam_kernel)
    if (tid < 32) {
        float a = lql[tid] * lkl[tid] + lql[tid + 32] * lkl[tid + 32];
        float b = lqr[tid] * lkr[tid] + lqr[tid + 32] * lkr[tid + 32];
#pragma unroll
        for (int off = 16; off > 0; off >>= 1) {
            a += __shfl_xor_sync(0xffffffffu, a, off);
            b += __shfl_xor_sync(0xffffffffu, b, off);
        }
        if (tid == 0) slam = expf(a) - expf(b) + 0.1f;
    }
    __syncthreads();
    const float lam = slam;

    const int b = blockIdx.x >> 6;
    const int s = ((blockIdx.x & 63) << 5) + sl;
    const size_t col = (size_t)b * EE * SS + s;
    const int e0 = ty << 5;                        // 32 e's per group

    float sum = 0.f, sq = 0.f;
    for (int e = e0; e < e0 + 32; ++e) {
        size_t idx = col + (size_t)e * SS;
        float c = al[idx] - lam * ar[idx];
        sum += c; sq += c * c;
    }
    ps[ty][sl] = sum; pq[ty][sl] = sq;
    __syncthreads();
    if (ty == 0) {
        float ts = 0.f, tq = 0.f;
#pragma unroll
        for (int r = 0; r < 32; ++r) { ts += ps[r][sl]; tq += pq[r][sl]; }
        float mu = ts * (1.f / EE);
        float var = tq * (1.f / EE) - mu * mu;
        smu[sl] = mu;
        srs[sl] = rsqrtf(var + 1e-5f);
    }
    __syncthreads();
    const float mu = smu[sl], rs = srs[sl];
    for (int e = e0; e < e0 + 32; ++e) {
        size_t idx = col + (size_t)e * SS;
        float c = al[idx] - lam * ar[idx];
        out[idx] = (c - mu) * rs * gg[e] + bbv[e];
    }
}

// ---------------------------------------------------------------------------
// Launch
// ---------------------------------------------------------------------------
static float* sym_addr(const void* symbol)
{
    void* p = nullptr;
    cudaGetSymbolAddress(&p, symbol);
    return (float*)p;
}

extern "C" void kernel_launch(void* const* d_in, const int* in_sizes, int n_in,
                              void* d_out, int out_size)
{
    const float* left  = (const float*)d_in[0];
    const float* right = (const float*)d_in[1];
    const float* Wq_l  = (const float*)d_in[2];
    const float* Wk_l  = (const float*)d_in[3];
    const float* Wv_l  = (const float*)d_in[4];
    const float* Wq_r  = (const float*)d_in[5];
    const float* Wk_r  = (const float*)d_in[6];
    const float* Wv_r  = (const float*)d_in[7];
    const float* Wo    = (const float*)d_in[8];
    const float* lql   = (const float*)d_in[9];
    const float* lkl   = (const float*)d_in[10];
    const float* lqr   = (const float*)d_in[11];
    const float* lkr   = (const float*)d_in[12];
    const float* ln_g  = (const float*)d_in[13];
    const float* ln_b  = (const float*)d_in[14];
    const float* W1    = (const float*)d_in[15];
    const float* b1    = (const float*)d_in[16];
    const float* W2    = (const float*)d_in[17];
    const float* b2    = (const float*)d_in[18];
    float* out = (float*)d_out;

    float* ql = sym_addr(g_ql); float* kl = sym_addr(g_kl); float* vl = sym_addr(g_vl);
    float* qr = sym_addr(g_qr); float* kr = sym_addr(g_kr); float* vr = sym_addr(g_vr);
    float* al = sym_addr(g_al); float* ar = sym_addr(g_ar);
    float* lno = sym_addr(g_lnout);
    float* h1 = sym_addr(g_h1);
    float* wf = sym_addr(g_wf);

    // D^-0.5 * log2(e): scores in log2 domain (softmax-invariant)
    const float qscale = 0.125f * 1.4426950408889634f;

    cudaFuncSetAttribute(gemm_tc, cudaFuncAttributeMaxDynamicSharedMemorySize,
                         GEMM_SMEM);
    cudaFuncSetAttribute(gemm_qkvwf, cudaFuncAttributeMaxDynamicSharedMemorySize,
                         GEMM_SMEM);
    cudaFuncSetAttribute(attn_mma, cudaFuncAttributeMaxDynamicSharedMemorySize,
                         ATTN_SMEM);

    dim3 blk(256);

    // QKV projections + Wf=W1@Wo fused into one launch (z = 0..12)
    gemm_qkvwf<<<dim3(SS / 128, EE / 128, 13), blk, GEMM_SMEM>>>(
        Wq_l, Wk_l, Wv_l, Wq_r, Wk_r, Wv_r, left, right, W1, Wo, wf,
        ql, kl, vl, qr, kr, vr, qscale);

    // attention: both paths in one launch (z = path*2 + b)
    attn_mma<<<dim3(SS / 128, HH, 2 * BB), 256, ATTN_SMEM>>>(
        ql, kl, vl, al, qr, kr, vr, ar);

    // combine + LN (lambda computed inline)
    ln_kernel<<<BB * (SS / 32), 1024>>>(al, ar, ln_g, ln_b,
                                        lql, lkl, lqr, lkr, lno);

    // fused (W1@Wo) + relu, then W2 straight into d_out ([B,E,S])
    gemm_tc<<<dim3(SS / 128, 2 * EE / 128, BB), blk, GEMM_SMEM>>>(
        wf, lno, h1, 2 * EE, EE, SS, b1, 1.f, 1);
    gemm_tc<<<dim3(SS / 128, EE / 128, BB), blk, GEMM_SMEM>>>(
        W2, h1, out, EE, 2 * EE, SS, b2, 1.f, 0);
}

// round 16
// speedup vs baseline: 1.1235x; 1.0361x over previous
#include <cuda_runtime.h>
#include <cuda_bf16.h>
#include <math.h>

// Problem constants
#define BB 2
#define EE 1024
#define SS 2048
#define HH 16
#define DD 64
#define BES (BB*EE*SS)          // 4,194,304 elements

// ---------------------------------------------------------------------------
// Scratch (device globals; no runtime allocation allowed)
// ---------------------------------------------------------------------------
__device__ float g_ql[BES], g_kl[BES], g_vl[BES];
__device__ float g_qr[BES], g_kr[BES], g_vr[BES];
__device__ float g_al[BES], g_ar[BES];
__device__ float g_lnout[BES];
__device__ float g_h1[2 * BES];
__device__ float g_wf[2 * EE * EE];

// ---------------------------------------------------------------------------
// bf16 split helpers
// ---------------------------------------------------------------------------
__device__ __forceinline__ unsigned bf2pack(float x, float y) {
    __nv_bfloat162 h = __floats2bfloat162_rn(x, y);
    return *reinterpret_cast<unsigned*>(&h);
}
__device__ __forceinline__ float bfhi(float x) {
    return __bfloat162float(__float2bfloat16(x));
}
__device__ __forceinline__ void mma_bf16(
    float& c0, float& c1, float& c2, float& c3,
    unsigned a0, unsigned a1, unsigned a2, unsigned a3,
    unsigned b0, unsigned b1)
{
    asm("mma.sync.aligned.m16n8k16.row.col.f32.bf16.bf16.f32 "
        "{%0,%1,%2,%3}, {%4,%5,%6,%7}, {%8,%9}, {%0,%1,%2,%3};"
        : "+f"(c0), "+f"(c1), "+f"(c2), "+f"(c3)
        : "r"(a0), "r"(a1), "r"(a2), "r"(a3), "r"(b0), "r"(b1));
}

// exp2 via FMA-pipe polynomial (degree-5, rel ~2e-6) — dodges MUFU ceiling.
__device__ __forceinline__ float exp2p(float z) {
    z = fmaxf(z, -100.f);
    float n = rintf(z);
    float f = z - n;
    float p = 0.00133335581f;
    p = fmaf(p, f, 0.00961812911f);
    p = fmaf(p, f, 0.05550410866f);
    p = fmaf(p, f, 0.24022650696f);
    p = fmaf(p, f, 0.69314718056f);
    p = fmaf(p, f, 1.0f);
    float sc = __int_as_float(((int)n + 127) << 23);
    return p * sc;
}

// ---------------------------------------------------------------------------
// Tensor-core GEMM body (3-product split-bf16 m16n8k16), double-buffered,
// two-pass compute. B fragments packed [bh0,bh1,bl0,bl1] per slot so pass-1
// is a single LDS.128 and the store a single STS.128 (halves B-path shared
// traffic; values and mma order identical).
// Per-buffer word layout: Ah[0..1023] Al[1024..2047] B[2048..4095]
// ---------------------------------------------------------------------------
#define GEMM_SMEM (2 * 4096 * 4)

__device__ __forceinline__ void gemm_body(
    const float* __restrict__ W, const float* __restrict__ Xb,
    float* __restrict__ Cb, int bm, int bn,
    int M, int K, int N, const float* __restrict__ bias, float alpha, int relu,
    unsigned* smp)
{
    const int t = threadIdx.x;
    const int lane = t & 31, wid = t >> 5;
    const int warpM = wid >> 2, warpN = wid & 3;

    float acc[4][4][4];
#pragma unroll
    for (int a = 0; a < 4; ++a)
#pragma unroll
        for (int b = 0; b < 4; ++b)
#pragma unroll
            for (int c = 0; c < 4; ++c) acc[a][b][c] = 0.f;

    const int amt = t >> 5, als = t & 31;
    const int amo = (amt << 4) + (als >> 2);
    const int ako = (als & 3) << 1;
    int bno[2], bko[2];
#pragma unroll
    for (int i = 0; i < 2; ++i) {
        int s = t + (i << 8), nt = s >> 5, ls = s & 31;
        bno[i] = (nt << 3) + (ls >> 2);
        bko[i] = (ls & 3) << 1;
    }

    float2 pa[4];
    float2 pb[2][2];

    auto loadG = [&](int k0) {
        const float* ap = W + (size_t)(bm + amo) * K + (k0 + ako);
        pa[0] = *(const float2*)ap;
        pa[1] = *(const float2*)(ap + (size_t)8 * K);
        pa[2] = *(const float2*)(ap + 8);
        pa[3] = *(const float2*)(ap + (size_t)8 * K + 8);
#pragma unroll
        for (int i = 0; i < 2; ++i) {
            const float* bp = Xb + (size_t)(k0 + bko[i]) * N + bn + bno[i];
            pb[i][0] = make_float2(bp[0], bp[N]);
            pb[i][1] = make_float2(bp[(size_t)8 * N], bp[(size_t)9 * N]);
        }
    };

    auto storeS = [&](int buf) {
        unsigned* Ah = smp + buf * 4096;
        unsigned* Al = smp + buf * 4096 + 1024;
        unsigned* Bs = smp + buf * 4096 + 2048;
        {
            unsigned h[4], l[4];
#pragma unroll
            for (int r = 0; r < 4; ++r) {
                float hx = bfhi(pa[r].x), hy = bfhi(pa[r].y);
                h[r] = bf2pack(pa[r].x, pa[r].y);
                l[r] = bf2pack(pa[r].x - hx, pa[r].y - hy);
            }
            *(uint4*)&Ah[t * 4] = make_uint4(h[0], h[1], h[2], h[3]);
            *(uint4*)&Al[t * 4] = make_uint4(l[0], l[1], l[2], l[3]);
        }
#pragma unroll
        for (int i = 0; i < 2; ++i) {
            int s = t + (i << 8);
            float hx = bfhi(pb[i][0].x), hy = bfhi(pb[i][0].y);
            unsigned h0 = bf2pack(pb[i][0].x, pb[i][0].y);
            unsigned l0 = bf2pack(pb[i][0].x - hx, pb[i][0].y - hy);
            hx = bfhi(pb[i][1].x); hy = bfhi(pb[i][1].y);
            unsigned h1 = bf2pack(pb[i][1].x, pb[i][1].y);
            unsigned l1 = bf2pack(pb[i][1].x - hx, pb[i][1].y - hy);
            *(uint4*)&Bs[s * 4] = make_uint4(h0, h1, l0, l1);
        }
    };

    // Two-pass compute: pass1 = Ah x (Bh, Bl); pass2 = Al x Bh.
    auto compute = [&](int buf) {
        const unsigned* Ah = smp + buf * 4096;
        const unsigned* Al = smp + buf * 4096 + 1024;
        const unsigned* Bs = smp + buf * 4096 + 2048;
        uint4 af[4];
#pragma unroll
        for (int mt = 0; mt < 4; ++mt)
            af[mt] = *(const uint4*)&Ah[((warpM * 4 + mt) * 32 + lane) * 4];
#pragma unroll
        for (int nt = 0; nt < 4; ++nt) {
            int idx = (warpN * 4 + nt) * 32 + lane;
            uint4 bq = *(const uint4*)&Bs[idx * 4];   // [bh0,bh1,bl0,bl1]
#pragma unroll
            for (int mt = 0; mt < 4; ++mt) {
                float* c = acc[mt][nt];
                mma_bf16(c[0], c[1], c[2], c[3],
                         af[mt].x, af[mt].y, af[mt].z, af[mt].w, bq.x, bq.y);
                mma_bf16(c[0], c[1], c[2], c[3],
                         af[mt].x, af[mt].y, af[mt].z, af[mt].w, bq.z, bq.w);
            }
        }
#pragma unroll
        for (int mt = 0; mt < 4; ++mt)
            af[mt] = *(const uint4*)&Al[((warpM * 4 + mt) * 32 + lane) * 4];
#pragma unroll
        for (int nt = 0; nt < 4; ++nt) {
            int idx = (warpN * 4 + nt) * 32 + lane;
            uint2 bh = *(const uint2*)&Bs[idx * 4];   // hi half only
#pragma unroll
            for (int mt = 0; mt < 4; ++mt) {
                float* c = acc[mt][nt];
                mma_bf16(c[0], c[1], c[2], c[3],
                         af[mt].x, af[mt].y, af[mt].z, af[mt].w, bh.x, bh.y);
            }
        }
    };

    const int kiters = K >> 4;
    loadG(0);
    storeS(0);
    __syncthreads();
    for (int it = 0; it < kiters; ++it) {
        const int cur = it & 1;
        if (it + 1 < kiters) loadG((it + 1) << 4);
        compute(cur);
        if (it + 1 < kiters) storeS(cur ^ 1);
        __syncthreads();
    }

    const int r = lane >> 2, j = lane & 3;
#pragma unroll
    for (int mt = 0; mt < 4; ++mt) {
        const int m0 = bm + warpM * 64 + mt * 16 + r;
        const float bv0 = bias ? bias[m0] : 0.f;
        const float bv1 = bias ? bias[m0 + 8] : 0.f;
#pragma unroll
        for (int nt = 0; nt < 4; ++nt) {
            const int n = bn + warpN * 32 + nt * 8 + j * 2;
            const float* c = acc[mt][nt];
            float r0 = alpha * c[0] + bv0, r1 = alpha * c[1] + bv0;
            float r2 = alpha * c[2] + bv1, r3 = alpha * c[3] + bv1;
            if (relu) {
                r0 = fmaxf(r0, 0.f); r1 = fmaxf(r1, 0.f);
                r2 = fmaxf(r2, 0.f); r3 = fmaxf(r3, 0.f);
            }
            *(float2*)&Cb[(size_t)m0 * N + n] = make_float2(r0, r1);
            *(float2*)&Cb[(size_t)(m0 + 8) * N + n] = make_float2(r2, r3);
        }
    }
}

__global__ __launch_bounds__(256, 2) void gemm_tc(
    const float* __restrict__ W, const float* __restrict__ X,
    float* __restrict__ C, int M, int K, int N,
    const float* __restrict__ bias, float alpha, int relu)
{
    extern __shared__ __align__(16) unsigned smp[];
    gemm_body(W, X + (size_t)blockIdx.z * K * N, C + (size_t)blockIdx.z * M * N,
              blockIdx.y << 7, blockIdx.x << 7, M, K, N, bias, alpha, relu, smp);
}

// QKV projections (z 0..11) + Wf=W1@Wo (z==12) fused in ONE launch.
__global__ __launch_bounds__(256, 2) void gemm_qkvwf(
    const float* __restrict__ Wq_l, const float* __restrict__ Wk_l,
    const float* __restrict__ Wv_l, const float* __restrict__ Wq_r,
    const float* __restrict__ Wk_r, const float* __restrict__ Wv_r,
    const float* __restrict__ left, const float* __restrict__ right,
    const float* __restrict__ W1, const float* __restrict__ Wo,
    float* __restrict__ wf,
    float* ql, float* kl, float* vl, float* qr, float* kr, float* vr,
    float qscale)
{
    extern __shared__ __align__(16) unsigned smp[];
    const int z = blockIdx.z;
    if (z == 12) {
        int tt = blockIdx.y * 16 + blockIdx.x;   // 0..127
        gemm_body(W1, Wo, wf, (tt >> 3) << 7, (tt & 7) << 7,
                  2 * EE, EE, EE, nullptr, 1.f, 0, smp);
        return;
    }
    const int which = z >> 1, b = z & 1;
    const float* Ws[6] = {Wq_l, Wk_l, Wv_l, Wq_r, Wk_r, Wv_r};
    float*       Cs[6] = {ql, kl, vl, qr, kr, vr};
    const float* X = (which < 3) ? left : right;
    const float alpha = (which == 0 || which == 3) ? qscale : 1.f;
    gemm_body(Ws[which], X + (size_t)b * EE * SS, Cs[which] + (size_t)b * EE * SS,
              blockIdx.y << 7, blockIdx.x << 7, EE, EE, SS, nullptr, alpha, 0, smp);
}

// ---------------------------------------------------------------------------
// Tensor-core flash attention (causal), split-bf16 3-product, FA2 fragment
// chaining, log2-domain softmax via exp2p. (verified, unchanged)
// ---------------------------------------------------------------------------
#define ATTN_SMEM (16384 * 4)

__global__ __launch_bounds__(256, 2) void attn_mma(
    const float* __restrict__ Qlp, const float* __restrict__ Klp,
    const float* __restrict__ Vlp, float* __restrict__ Olp,
    const float* __restrict__ Qrp, const float* __restrict__ Krp,
    const float* __restrict__ Vrp, float* __restrict__ Orp)
{
    extern __shared__ __align__(16) unsigned smw[];
    unsigned* Qh = smw;            // 4096
    unsigned* Qlo = smw + 4096;    // 4096
    unsigned* Kh = smw + 8192;     // 2048
    unsigned* Klo = smw + 10240;   // 2048
    unsigned* Vh = smw + 12288;    // 2048
    unsigned* Vlo = smw + 14336;   // 2048

    const int tid = threadIdx.x;
    const int lane = tid & 31, w = tid >> 5;
    const int path = blockIdx.z >> 1;
    const int bz = blockIdx.z & 1;
    const float* Q = path ? Qrp : Qlp;
    const float* Kg = path ? Krp : Klp;
    const float* V = path ? Vrp : Vlp;
    float* O = path ? Orp : Olp;

    const int qt = (gridDim.x - 1) - blockIdx.x;
    const int q0 = qt << 7;
    const size_t base = ((size_t)bz * EE + (size_t)blockIdx.y * DD) * SS;
    const float* Qp = Q + base;
    const float* Kp = Kg + base;
    const float* Vp = V + base;

#pragma unroll
    for (int i = 0; i < 4; ++i) {
        int s = tid + (i << 8);
        int ls = s & 31, kc = (s >> 5) & 3, wq = s >> 7;
        int qr_ = q0 + (wq << 4) + (ls >> 2);
        int d0 = (kc << 4) + ((ls & 3) << 1);
        const float* p00 = Qp + (size_t)d0 * SS + qr_;
        float f0a = p00[0],              f0b = p00[SS];
        float f1a = p00[8],              f1b = p00[SS + 8];
        float f2a = p00[(size_t)8 * SS], f2b = p00[(size_t)9 * SS];
        float f3a = p00[(size_t)8 * SS + 8], f3b = p00[(size_t)9 * SS + 8];
        unsigned h0 = bf2pack(f0a, f0b), h1 = bf2pack(f1a, f1b);
        unsigned h2 = bf2pack(f2a, f2b), h3 = bf2pack(f3a, f3b);
        unsigned l0 = bf2pack(f0a - bfhi(f0a), f0b - bfhi(f0b));
        unsigned l1 = bf2pack(f1a - bfhi(f1a), f1b - bfhi(f1b));
        unsigned l2 = bf2pack(f2a - bfhi(f2a), f2b - bfhi(f2b));
        unsigned l3 = bf2pack(f3a - bfhi(f3a), f3b - bfhi(f3b));
        *(uint4*)&Qh[s * 4]  = make_uint4(h0, h1, h2, h3);
        *(uint4*)&Qlo[s * 4] = make_uint4(l0, l1, l2, l3);
    }

    float o[8][4];
#pragma unroll
    for (int i = 0; i < 8; ++i)
#pragma unroll
        for (int j = 0; j < 4; ++j) o[i][j] = 0.f;
    float m0 = -1e30f, m1 = -1e30f, l0s = 0.f, l1s = 0.f;

    const int qg = q0 + (w << 4) + (lane >> 2);
    const int ntile = qt * 2 + 2;

    for (int kt = 0; kt < ntile; ++kt) {
        const int t0 = kt << 6;
        __syncthreads();
#pragma unroll
        for (int i = 0; i < 4; ++i) {
            int s = tid + (i << 8);
            int ls = s & 31, kc = (s >> 5) & 3, nt = s >> 7;
            int tt = t0 + (nt << 3) + (ls >> 2);
            int d0 = (kc << 4) + ((ls & 3) << 1);
            const float* p00 = Kp + (size_t)d0 * SS + tt;
            float f0a = p00[0], f0b = p00[SS];
            float f1a = p00[(size_t)8 * SS], f1b = p00[(size_t)9 * SS];
            *(uint2*)&Kh[s * 2] = make_uint2(bf2pack(f0a, f0b), bf2pack(f1a, f1b));
            *(uint2*)&Klo[s * 2] = make_uint2(
                bf2pack(f0a - bfhi(f0a), f0b - bfhi(f0b)),
                bf2pack(f1a - bfhi(f1a), f1b - bfhi(f1b)));
        }
#pragma unroll
        for (int i = 0; i < 4; ++i) {
            int s = tid + (i << 8);
            int ls = s & 31, tc = (s >> 5) & 3, ndt = s >> 7;
            int d = (ndt << 3) + (ls >> 2);
            int tt = t0 + (tc << 4) + ((ls & 3) << 1);
            const float* p00 = Vp + (size_t)d * SS + tt;
            float2 v0 = *(const float2*)p00;
            float2 v1 = *(const float2*)(p00 + 8);
            *(uint2*)&Vh[s * 2] = make_uint2(bf2pack(v0.x, v0.y), bf2pack(v1.x, v1.y));
            *(uint2*)&Vlo[s * 2] = make_uint2(
                bf2pack(v0.x - bfhi(v0.x), v0.y - bfhi(v0.y)),
                bf2pack(v1.x - bfhi(v1.x), v1.y - bfhi(v1.y)));
        }
        __syncthreads();

        float sreg[8][4];
#pragma unroll
        for (int i = 0; i < 8; ++i)
#pragma unroll
            for (int j = 0; j < 4; ++j) sreg[i][j] = 0.f;
#pragma unroll
        for (int kc = 0; kc < 4; ++kc) {
            int ai = ((w * 4 + kc) * 32 + lane);
            uint4 ah = *(const uint4*)&Qh[ai * 4];
            uint4 al = *(const uint4*)&Qlo[ai * 4];
#pragma unroll
            for (int nt = 0; nt < 8; ++nt) {
                int bi = ((nt * 4 + kc) * 32 + lane);
                uint2 bh = *(const uint2*)&Kh[bi * 2];
                uint2 bl = *(const uint2*)&Klo[bi * 2];
                float* c = sreg[nt];
                mma_bf16(c[0], c[1], c[2], c[3], ah.x, ah.y, ah.z, ah.w, bh.x, bh.y);
                mma_bf16(c[0], c[1], c[2], c[3], ah.x, ah.y, ah.z, ah.w, bl.x, bl.y);
                mma_bf16(c[0], c[1], c[2], c[3], al.x, al.y, al.z, al.w, bh.x, bh.y);
            }
        }

        float mx0 = m0, mx1 = m1;
#pragma unroll
        for (int nt = 0; nt < 8; ++nt) {
            int tb = t0 + (nt << 3) + ((lane & 3) << 1);
            if (tb > qg)     sreg[nt][0] = -1e30f;
            if (tb + 1 > qg) sreg[nt][1] = -1e30f;
            if (tb > qg + 8)     sreg[nt][2] = -1e30f;
            if (tb + 1 > qg + 8) sreg[nt][3] = -1e30f;
            mx0 = fmaxf(mx0, fmaxf(sreg[nt][0], sreg[nt][1]));
            mx1 = fmaxf(mx1, fmaxf(sreg[nt][2], sreg[nt][3]));
        }
        mx0 = fmaxf(mx0, __shfl_xor_sync(0xffffffffu, mx0, 1));
        mx0 = fmaxf(mx0, __shfl_xor_sync(0xffffffffu, mx0, 2));
        mx1 = fmaxf(mx1, __shfl_xor_sync(0xffffffffu, mx1, 1));
        mx1 = fmaxf(mx1, __shfl_xor_sync(0xffffffffu, mx1, 2));
        float corr0 = exp2p(m0 - mx0), corr1 = exp2p(m1 - mx1);
        m0 = mx0; m1 = mx1;
        l0s *= corr0; l1s *= corr1;
#pragma unroll
        for (int nt = 0; nt < 8; ++nt) {
            o[nt][0] *= corr0; o[nt][1] *= corr0;
            o[nt][2] *= corr1; o[nt][3] *= corr1;
        }
        float ls0 = 0.f, ls1 = 0.f;
#pragma unroll
        for (int nt = 0; nt < 8; ++nt) {
            float p0 = exp2p(sreg[nt][0] - mx0);
            float p1 = exp2p(sreg[nt][1] - mx0);
            float p2 = exp2p(sreg[nt][2] - mx1);
            float p3 = exp2p(sreg[nt][3] - mx1);
            sreg[nt][0] = p0; sreg[nt][1] = p1;
            sreg[nt][2] = p2; sreg[nt][3] = p3;
            ls0 += p0 + p1; ls1 += p2 + p3;
        }
        ls0 += __shfl_xor_sync(0xffffffffu, ls0, 1);
        ls0 += __shfl_xor_sync(0xffffffffu, ls0, 2);
        ls1 += __shfl_xor_sync(0xffffffffu, ls1, 1);
        ls1 += __shfl_xor_sync(0xffffffffu, ls1, 2);
        l0s += ls0; l1s += ls1;

#pragma unroll
        for (int j = 0; j < 4; ++j) {
            float* pA = sreg[2 * j];
            float* pB = sreg[2 * j + 1];
            unsigned ah0 = bf2pack(pA[0], pA[1]);
            unsigned ah1 = bf2pack(pA[2], pA[3]);
            unsigned ah2 = bf2pack(pB[0], pB[1]);
            unsigned ah3 = bf2pack(pB[2], pB[3]);
            unsigned al0 = bf2pack(pA[0] - bfhi(pA[0]), pA[1] - bfhi(pA[1]));
            unsigned al1 = bf2pack(pA[2] - bfhi(pA[2]), pA[3] - bfhi(pA[3]));
            unsigned al2 = bf2pack(pB[0] - bfhi(pB[0]), pB[1] - bfhi(pB[1]));
            unsigned al3 = bf2pack(pB[2] - bfhi(pB[2]), pB[3] - bfhi(pB[3]));
#pragma unroll
            for (int nt = 0; nt < 8; ++nt) {
                int bi = ((nt * 4 + j) * 32 + lane);
                uint2 bh = *(const uint2*)&Vh[bi * 2];
                uint2 bl = *(const uint2*)&Vlo[bi * 2];
                float* c = o[nt];
                mma_bf16(c[0], c[1], c[2], c[3], ah0, ah1, ah2, ah3, bh.x, bh.y);
                mma_bf16(c[0], c[1], c[2], c[3], ah0, ah1, ah2, ah3, bl.x, bl.y);
                mma_bf16(c[0], c[1], c[2], c[3], al0, al1, al2, al3, bh.x, bh.y);
            }
        }
    }

    const float inv0 = 1.f / l0s, inv1 = 1.f / l1s;
    float* Op = O + base;
#pragma unroll
    for (int nt = 0; nt < 8; ++nt) {
        int d = (nt << 3) + ((lane & 3) << 1);
        Op[(size_t)d * SS + qg]       = o[nt][0] * inv0;
        Op[(size_t)(d + 1) * SS + qg] = o[nt][1] * inv0;
        Op[(size_t)d * SS + qg + 8]       = o[nt][2] * inv1;
        Op[(size_t)(d + 1) * SS + qg + 8] = o[nt][3] * inv1;
    }
}

// ---------------------------------------------------------------------------
// combined = attn_l - lam*attn_r; LayerNorm over E; lambda inline (warp 0).
// 1024 threads = 32 e-groups x 32 s; grid = B*S/32 = 128.
// ---------------------------------------------------------------------------
__global__ __launch_bounds__(1024) void ln_kernel(
    const float* __restrict__ al, const float* __restrict__ ar,
    const float* __restrict__ gg, const float* __restrict__ bbv,
    const float* __restrict__ lql, const float* __restrict__ lkl,
    const float* __restrict__ lqr, const float* __restrict__ lkr,
    float* __restrict__ out)
{
    __shared__ float ps[32][32], pq[32][32], smu[32], srs[32], slam;
    const int tid = threadIdx.x;
    const int ty = tid >> 5, sl = tid & 31;

    if (tid < 32) {
        float a = lql[tid] * lkl[tid] + lql[tid + 32] * lkl[tid + 32];
        float b = lqr[tid] * lkr[tid] + lqr[tid + 32] * lkr[tid + 32];
#pragma unroll
        for (int off = 16; off > 0; off >>= 1) {
            a += __shfl_xor_sync(0xffffffffu, a, off);
            b += __shfl_xor_sync(0xffffffffu, b, off);
        }
        if (tid == 0) slam = expf(a) - expf(b) + 0.1f;
    }
    __syncthreads();
    const float lam = slam;

    const int b = blockIdx.x >> 6;
    const int s = ((blockIdx.x & 63) << 5) + sl;
    const size_t col = (size_t)b * EE * SS + s;
    const int e0 = ty << 5;

    float sum = 0.f, sq = 0.f;
    for (int e = e0; e < e0 + 32; ++e) {
        size_t idx = col + (size_t)e * SS;
        float c = al[idx] - lam * ar[idx];
        sum += c; sq += c * c;
    }
    ps[ty][sl] = sum; pq[ty][sl] = sq;
    __syncthreads();
    if (ty == 0) {
        float ts = 0.f, tq = 0.f;
#pragma unroll
        for (int r = 0; r < 32; ++r) { ts += ps[r][sl]; tq += pq[r][sl]; }
        float mu = ts * (1.f / EE);
        float var = tq * (1.f / EE) - mu * mu;
        smu[sl] = mu;
        srs[sl] = rsqrtf(var + 1e-5f);
    }
    __syncthreads();
    const float mu = smu[sl], rs = srs[sl];
    for (int e = e0; e < e0 + 32; ++e) {
        size_t idx = col + (size_t)e * SS;
        float c = al[idx] - lam * ar[idx];
        out[idx] = (c - mu) * rs * gg[e] + bbv[e];
    }
}

// ---------------------------------------------------------------------------
// Launch
// ---------------------------------------------------------------------------
static float* sym_addr(const void* symbol)
{
    void* p = nullptr;
    cudaGetSymbolAddress(&p, symbol);
    return (float*)p;
}

extern "C" void kernel_launch(void* const* d_in, const int* in_sizes, int n_in,
                              void* d_out, int out_size)
{
    const float* left  = (const float*)d_in[0];
    const float* right = (const float*)d_in[1];
    const float* Wq_l  = (const float*)d_in[2];
    const float* Wk_l  = (const float*)d_in[3];
    const float* Wv_l  = (const float*)d_in[4];
    const float* Wq_r  = (const float*)d_in[5];
    const float* Wk_r  = (const float*)d_in[6];
    const float* Wv_r  = (const float*)d_in[7];
    const float* Wo    = (const float*)d_in[8];
    const float* lql   = (const float*)d_in[9];
    const float* lkl   = (const float*)d_in[10];
    const float* lqr   = (const float*)d_in[11];
    const float* lkr   = (const float*)d_in[12];
    const float* ln_g  = (const float*)d_in[13];
    const float* ln_b  = (const float*)d_in[14];
    const float* W1    = (const float*)d_in[15];
    const float* b1    = (const float*)d_in[16];
    const float* W2    = (const float*)d_in[17];
    const float* b2    = (const float*)d_in[18];
    float* out = (float*)d_out;

    float* ql = sym_addr(g_ql); float* kl = sym_addr(g_kl); float* vl = sym_addr(g_vl);
    float* qr = sym_addr(g_qr); float* kr = sym_addr(g_kr); float* vr = sym_addr(g_vr);
    float* al = sym_addr(g_al); float* ar = sym_addr(g_ar);
    float* lno = sym_addr(g_lnout);
    float* h1 = sym_addr(g_h1);
    float* wf = sym_addr(g_wf);

    // D^-0.5 * log2(e): scores in log2 domain (softmax-invariant)
    const float qscale = 0.125f * 1.4426950408889634f;

    cudaFuncSetAttribute(gemm_tc, cudaFuncAttributeMaxDynamicSharedMemorySize,
                         GEMM_SMEM);
    cudaFuncSetAttribute(gemm_qkvwf, cudaFuncAttributeMaxDynamicSharedMemorySize,
                         GEMM_SMEM);
    cudaFuncSetAttribute(attn_mma, cudaFuncAttributeMaxDynamicSharedMemorySize,
                         ATTN_SMEM);

    dim3 blk(256);

    // QKV projections + Wf=W1@Wo fused into one launch (z = 0..12)
    gemm_qkvwf<<<dim3(SS / 128, EE / 128, 13), blk, GEMM_SMEM>>>(
        Wq_l, Wk_l, Wv_l, Wq_r, Wk_r, Wv_r, left, right, W1, Wo, wf,
        ql, kl, vl, qr, kr, vr, qscale);

    // attention: both paths in one launch (z = path*2 + b)
    attn_mma<<<dim3(SS / 128, HH, 2 * BB), 256, ATTN_SMEM>>>(
        ql, kl, vl, al, qr, kr, vr, ar);

    // combine + LN (lambda computed inline)
    ln_kernel<<<BB * (SS / 32), 1024>>>(al, ar, ln_g, ln_b,
                                        lql, lkl, lqr, lkr, lno);

    // fused (W1@Wo) + relu, then W2 straight into d_out ([B,E,S])
    gemm_tc<<<dim3(SS / 128, 2 * EE / 128, BB), blk, GEMM_SMEM>>>(
        wf, lno, h1, 2 * EE, EE, SS, b1, 1.f, 1);
    gemm_tc<<<dim3(SS / 128, EE / 128, BB), blk, GEMM_SMEM>>>(
        W2, h1, out, EE, 2 * EE, SS, b2, 1.f, 0);
}

// round 17
// speedup vs baseline: 1.1301x; 1.0058x over previous
#include <cuda_runtime.h>
#include <cuda_bf16.h>
#include <math.h>

// Problem constants
#define BB 2
#define EE 1024
#define SS 2048
#define HH 16
#define DD 64
#define BES (BB*EE*SS)          // 4,194,304 elements

// ---------------------------------------------------------------------------
// Scratch (device globals; no runtime allocation allowed)
// ---------------------------------------------------------------------------
__device__ float g_ql[BES], g_kl[BES], g_vl[BES];
__device__ float g_qr[BES], g_kr[BES], g_vr[BES];
__device__ float g_al[BES], g_ar[BES];
__device__ float g_lnout[BES];
__device__ float g_h1[2 * BES];
__device__ float g_wf[2 * EE * EE];

// ---------------------------------------------------------------------------
// bf16 split helpers
// ---------------------------------------------------------------------------
__device__ __forceinline__ unsigned bf2pack(float x, float y) {
    __nv_bfloat162 h = __floats2bfloat162_rn(x, y);
    return *reinterpret_cast<unsigned*>(&h);
}
__device__ __forceinline__ float bfhi(float x) {
    return __bfloat162float(__float2bfloat16(x));
}
__device__ __forceinline__ void mma_bf16(
    float& c0, float& c1, float& c2, float& c3,
    unsigned a0, unsigned a1, unsigned a2, unsigned a3,
    unsigned b0, unsigned b1)
{
    asm("mma.sync.aligned.m16n8k16.row.col.f32.bf16.bf16.f32 "
        "{%0,%1,%2,%3}, {%4,%5,%6,%7}, {%8,%9}, {%0,%1,%2,%3};"
        : "+f"(c0), "+f"(c1), "+f"(c2), "+f"(c3)
        : "r"(a0), "r"(a1), "r"(a2), "r"(a3), "r"(b0), "r"(b1));
}

// exp2 via FMA-pipe polynomial (degree-5, rel ~2e-6) — dodges MUFU ceiling.
__device__ __forceinline__ float exp2p(float z) {
    z = fmaxf(z, -100.f);
    float n = rintf(z);
    float f = z - n;
    float p = 0.00133335581f;
    p = fmaf(p, f, 0.00961812911f);
    p = fmaf(p, f, 0.05550410866f);
    p = fmaf(p, f, 0.24022650696f);
    p = fmaf(p, f, 0.69314718056f);
    p = fmaf(p, f, 1.0f);
    float sc = __int_as_float(((int)n + 127) << 23);
    return p * sc;
}

// ---------------------------------------------------------------------------
// Tensor-core GEMM body (3-product split-bf16 m16n8k16), double-buffered,
// two-pass compute, interleaved B slots [bh0,bh1,bl0,bl1].
// Per-buffer word layout: Ah[0..1023] Al[1024..2047] B[2048..4095]
// (round-16 verified; measured best)
// ---------------------------------------------------------------------------
#define GEMM_SMEM (2 * 4096 * 4)

__device__ __forceinline__ void gemm_body(
    const float* __restrict__ W, const float* __restrict__ Xb,
    float* __restrict__ Cb, int bm, int bn,
    int M, int K, int N, const float* __restrict__ bias, float alpha, int relu,
    unsigned* smp)
{
    const int t = threadIdx.x;
    const int lane = t & 31, wid = t >> 5;
    const int warpM = wid >> 2, warpN = wid & 3;

    float acc[4][4][4];
#pragma unroll
    for (int a = 0; a < 4; ++a)
#pragma unroll
        for (int b = 0; b < 4; ++b)
#pragma unroll
            for (int c = 0; c < 4; ++c) acc[a][b][c] = 0.f;

    const int amt = t >> 5, als = t & 31;
    const int amo = (amt << 4) + (als >> 2);
    const int ako = (als & 3) << 1;
    int bno[2], bko[2];
#pragma unroll
    for (int i = 0; i < 2; ++i) {
        int s = t + (i << 8), nt = s >> 5, ls = s & 31;
        bno[i] = (nt << 3) + (ls >> 2);
        bko[i] = (ls & 3) << 1;
    }

    float2 pa[4];
    float2 pb[2][2];

    auto loadG = [&](int k0) {
        const float* ap = W + (size_t)(bm + amo) * K + (k0 + ako);
        pa[0] = *(const float2*)ap;
        pa[1] = *(const float2*)(ap + (size_t)8 * K);
        pa[2] = *(const float2*)(ap + 8);
        pa[3] = *(const float2*)(ap + (size_t)8 * K + 8);
#pragma unroll
        for (int i = 0; i < 2; ++i) {
            const float* bp = Xb + (size_t)(k0 + bko[i]) * N + bn + bno[i];
            pb[i][0] = make_float2(bp[0], bp[N]);
            pb[i][1] = make_float2(bp[(size_t)8 * N], bp[(size_t)9 * N]);
        }
    };

    auto storeS = [&](int buf) {
        unsigned* Ah = smp + buf * 4096;
        unsigned* Al = smp + buf * 4096 + 1024;
        unsigned* Bs = smp + buf * 4096 + 2048;
        {
            unsigned h[4], l[4];
#pragma unroll
            for (int r = 0; r < 4; ++r) {
                float hx = bfhi(pa[r].x), hy = bfhi(pa[r].y);
                h[r] = bf2pack(pa[r].x, pa[r].y);
                l[r] = bf2pack(pa[r].x - hx, pa[r].y - hy);
            }
            *(uint4*)&Ah[t * 4] = make_uint4(h[0], h[1], h[2], h[3]);
            *(uint4*)&Al[t * 4] = make_uint4(l[0], l[1], l[2], l[3]);
        }
#pragma unroll
        for (int i = 0; i < 2; ++i) {
            int s = t + (i << 8);
            float hx = bfhi(pb[i][0].x), hy = bfhi(pb[i][0].y);
            unsigned h0 = bf2pack(pb[i][0].x, pb[i][0].y);
            unsigned l0 = bf2pack(pb[i][0].x - hx, pb[i][0].y - hy);
            hx = bfhi(pb[i][1].x); hy = bfhi(pb[i][1].y);
            unsigned h1 = bf2pack(pb[i][1].x, pb[i][1].y);
            unsigned l1 = bf2pack(pb[i][1].x - hx, pb[i][1].y - hy);
            *(uint4*)&Bs[s * 4] = make_uint4(h0, h1, l0, l1);
        }
    };

    auto compute = [&](int buf) {
        const unsigned* Ah = smp + buf * 4096;
        const unsigned* Al = smp + buf * 4096 + 1024;
        const unsigned* Bs = smp + buf * 4096 + 2048;
        uint4 af[4];
#pragma unroll
        for (int mt = 0; mt < 4; ++mt)
            af[mt] = *(const uint4*)&Ah[((warpM * 4 + mt) * 32 + lane) * 4];
#pragma unroll
        for (int nt = 0; nt < 4; ++nt) {
            int idx = (warpN * 4 + nt) * 32 + lane;
            uint4 bq = *(const uint4*)&Bs[idx * 4];   // [bh0,bh1,bl0,bl1]
#pragma unroll
            for (int mt = 0; mt < 4; ++mt) {
                float* c = acc[mt][nt];
                mma_bf16(c[0], c[1], c[2], c[3],
                         af[mt].x, af[mt].y, af[mt].z, af[mt].w, bq.x, bq.y);
                mma_bf16(c[0], c[1], c[2], c[3],
                         af[mt].x, af[mt].y, af[mt].z, af[mt].w, bq.z, bq.w);
            }
        }
#pragma unroll
        for (int mt = 0; mt < 4; ++mt)
            af[mt] = *(const uint4*)&Al[((warpM * 4 + mt) * 32 + lane) * 4];
#pragma unroll
        for (int nt = 0; nt < 4; ++nt) {
            int idx = (warpN * 4 + nt) * 32 + lane;
            uint2 bh = *(const uint2*)&Bs[idx * 4];   // hi half only
#pragma unroll
            for (int mt = 0; mt < 4; ++mt) {
                float* c = acc[mt][nt];
                mma_bf16(c[0], c[1], c[2], c[3],
                         af[mt].x, af[mt].y, af[mt].z, af[mt].w, bh.x, bh.y);
            }
        }
    };

    const int kiters = K >> 4;
    loadG(0);
    storeS(0);
    __syncthreads();
    for (int it = 0; it < kiters; ++it) {
        const int cur = it & 1;
        if (it + 1 < kiters) loadG((it + 1) << 4);
        compute(cur);
        if (it + 1 < kiters) storeS(cur ^ 1);
        __syncthreads();
    }

    const int r = lane >> 2, j = lane & 3;
#pragma unroll
    for (int mt = 0; mt < 4; ++mt) {
        const int m0 = bm + warpM * 64 + mt * 16 + r;
        const float bv0 = bias ? bias[m0] : 0.f;
        const float bv1 = bias ? bias[m0 + 8] : 0.f;
#pragma unroll
        for (int nt = 0; nt < 4; ++nt) {
            const int n = bn + warpN * 32 + nt * 8 + j * 2;
            const float* c = acc[mt][nt];
            float r0 = alpha * c[0] + bv0, r1 = alpha * c[1] + bv0;
            float r2 = alpha * c[2] + bv1, r3 = alpha * c[3] + bv1;
            if (relu) {
                r0 = fmaxf(r0, 0.f); r1 = fmaxf(r1, 0.f);
                r2 = fmaxf(r2, 0.f); r3 = fmaxf(r3, 0.f);
            }
            *(float2*)&Cb[(size_t)m0 * N + n] = make_float2(r0, r1);
            *(float2*)&Cb[(size_t)(m0 + 8) * N + n] = make_float2(r2, r3);
        }
    }
}

__global__ __launch_bounds__(256, 2) void gemm_tc(
    const float* __restrict__ W, const float* __restrict__ X,
    float* __restrict__ C, int M, int K, int N,
    const float* __restrict__ bias, float alpha, int relu)
{
    extern __shared__ __align__(16) unsigned smp[];
    gemm_body(W, X + (size_t)blockIdx.z * K * N, C + (size_t)blockIdx.z * M * N,
              blockIdx.y << 7, blockIdx.x << 7, M, K, N, bias, alpha, relu, smp);
}

// QKV projections (z 0..11) + Wf=W1@Wo (z==12) fused in ONE launch.
__global__ __launch_bounds__(256, 2) void gemm_qkvwf(
    const float* __restrict__ Wq_l, const float* __restrict__ Wk_l,
    const float* __restrict__ Wv_l, const float* __restrict__ Wq_r,
    const float* __restrict__ Wk_r, const float* __restrict__ Wv_r,
    const float* __restrict__ left, const float* __restrict__ right,
    const float* __restrict__ W1, const float* __restrict__ Wo,
    float* __restrict__ wf,
    float* ql, float* kl, float* vl, float* qr, float* kr, float* vr,
    float qscale)
{
    extern __shared__ __align__(16) unsigned smp[];
    const int z = blockIdx.z;
    if (z == 12) {
        int tt = blockIdx.y * 16 + blockIdx.x;   // 0..127
        gemm_body(W1, Wo, wf, (tt >> 3) << 7, (tt & 7) << 7,
                  2 * EE, EE, EE, nullptr, 1.f, 0, smp);
        return;
    }
    const int which = z >> 1, b = z & 1;
    const float* Ws[6] = {Wq_l, Wk_l, Wv_l, Wq_r, Wk_r, Wv_r};
    float*       Cs[6] = {ql, kl, vl, qr, kr, vr};
    const float* X = (which < 3) ? left : right;
    const float alpha = (which == 0 || which == 3) ? qscale : 1.f;
    gemm_body(Ws[which], X + (size_t)b * EE * SS, Cs[which] + (size_t)b * EE * SS,
              blockIdx.y << 7, blockIdx.x << 7, EE, EE, SS, nullptr, alpha, 0, smp);
}

// ---------------------------------------------------------------------------
// Tensor-core flash attention (causal), split-bf16 3-product, FA2 fragment
// chaining, log2-domain softmax via exp2p. K and V fragment slots now
// interleaved [h0,h1,l0,l1] -> one LDS.128 per slot read, one STS.128 per
// slot write (same values, same mma order; numerically identical).
// SMEM words: Qh[0..4095] Qlo[4096..8191] Kp[8192..12287] Vp[12288..16383]
// ---------------------------------------------------------------------------
#define ATTN_SMEM (16384 * 4)

__global__ __launch_bounds__(256, 2) void attn_mma(
    const float* __restrict__ Qlp, const float* __restrict__ Klp,
    const float* __restrict__ Vlp, float* __restrict__ Olp,
    const float* __restrict__ Qrp, const float* __restrict__ Krp,
    const float* __restrict__ Vrp, float* __restrict__ Orp)
{
    extern __shared__ __align__(16) unsigned smw[];
    unsigned* Qh = smw;            // 4096
    unsigned* Qlo = smw + 4096;    // 4096
    unsigned* Kp4 = smw + 8192;    // 4096: slot*4 = [kh0,kh1,kl0,kl1]
    unsigned* Vp4 = smw + 12288;   // 4096: slot*4 = [vh0,vh1,vl0,vl1]

    const int tid = threadIdx.x;
    const int lane = tid & 31, w = tid >> 5;
    const int path = blockIdx.z >> 1;
    const int bz = blockIdx.z & 1;
    const float* Q = path ? Qrp : Qlp;
    const float* Kg = path ? Krp : Klp;
    const float* V = path ? Vrp : Vlp;
    float* O = path ? Orp : Olp;

    const int qt = (gridDim.x - 1) - blockIdx.x;
    const int q0 = qt << 7;
    const size_t base = ((size_t)bz * EE + (size_t)blockIdx.y * DD) * SS;
    const float* Qp = Q + base;
    const float* Kp = Kg + base;
    const float* Vp = V + base;

#pragma unroll
    for (int i = 0; i < 4; ++i) {
        int s = tid + (i << 8);
        int ls = s & 31, kc = (s >> 5) & 3, wq = s >> 7;
        int qr_ = q0 + (wq << 4) + (ls >> 2);
        int d0 = (kc << 4) + ((ls & 3) << 1);
        const float* p00 = Qp + (size_t)d0 * SS + qr_;
        float f0a = p00[0],              f0b = p00[SS];
        float f1a = p00[8],              f1b = p00[SS + 8];
        float f2a = p00[(size_t)8 * SS], f2b = p00[(size_t)9 * SS];
        float f3a = p00[(size_t)8 * SS + 8], f3b = p00[(size_t)9 * SS + 8];
        unsigned h0 = bf2pack(f0a, f0b), h1 = bf2pack(f1a, f1b);
        unsigned h2 = bf2pack(f2a, f2b), h3 = bf2pack(f3a, f3b);
        unsigned l0 = bf2pack(f0a - bfhi(f0a), f0b - bfhi(f0b));
        unsigned l1 = bf2pack(f1a - bfhi(f1a), f1b - bfhi(f1b));
        unsigned l2 = bf2pack(f2a - bfhi(f2a), f2b - bfhi(f2b));
        unsigned l3 = bf2pack(f3a - bfhi(f3a), f3b - bfhi(f3b));
        *(uint4*)&Qh[s * 4]  = make_uint4(h0, h1, h2, h3);
        *(uint4*)&Qlo[s * 4] = make_uint4(l0, l1, l2, l3);
    }

    float o[8][4];
#pragma unroll
    for (int i = 0; i < 8; ++i)
#pragma unroll
        for (int j = 0; j < 4; ++j) o[i][j] = 0.f;
    float m0 = -1e30f, m1 = -1e30f, l0s = 0.f, l1s = 0.f;

    const int qg = q0 + (w << 4) + (lane >> 2);
    const int ntile = qt * 2 + 2;

    for (int kt = 0; kt < ntile; ++kt) {
        const int t0 = kt << 6;
        __syncthreads();
        // K loader: one STS.128 per slot
#pragma unroll
        for (int i = 0; i < 4; ++i) {
            int s = tid + (i << 8);
            int ls = s & 31, kc = (s >> 5) & 3, nt = s >> 7;
            int tt = t0 + (nt << 3) + (ls >> 2);
            int d0 = (kc << 4) + ((ls & 3) << 1);
            const float* p00 = Kp + (size_t)d0 * SS + tt;
            float f0a = p00[0], f0b = p00[SS];
            float f1a = p00[(size_t)8 * SS], f1b = p00[(size_t)9 * SS];
            *(uint4*)&Kp4[s * 4] = make_uint4(
                bf2pack(f0a, f0b), bf2pack(f1a, f1b),
                bf2pack(f0a - bfhi(f0a), f0b - bfhi(f0b)),
                bf2pack(f1a - bfhi(f1a), f1b - bfhi(f1b)));
        }
        // V loader: one STS.128 per slot
#pragma unroll
        for (int i = 0; i < 4; ++i) {
            int s = tid + (i << 8);
            int ls = s & 31, tc = (s >> 5) & 3, ndt = s >> 7;
            int d = (ndt << 3) + (ls >> 2);
            int tt = t0 + (tc << 4) + ((ls & 3) << 1);
            const float* p00 = Vp + (size_t)d * SS + tt;
            float2 v0 = *(const float2*)p00;
            float2 v1 = *(const float2*)(p00 + 8);
            *(uint4*)&Vp4[s * 4] = make_uint4(
                bf2pack(v0.x, v0.y), bf2pack(v1.x, v1.y),
                bf2pack(v0.x - bfhi(v0.x), v0.y - bfhi(v0.y)),
                bf2pack(v1.x - bfhi(v1.x), v1.y - bfhi(v1.y)));
        }
        __syncthreads();

        float sreg[8][4];
#pragma unroll
        for (int i = 0; i < 8; ++i)
#pragma unroll
            for (int j = 0; j < 4; ++j) sreg[i][j] = 0.f;
#pragma unroll
        for (int kc = 0; kc < 4; ++kc) {
            int ai = ((w * 4 + kc) * 32 + lane);
            uint4 ah = *(const uint4*)&Qh[ai * 4];
            uint4 al = *(const uint4*)&Qlo[ai * 4];
#pragma unroll
            for (int nt = 0; nt < 8; ++nt) {
                int bi = ((nt * 4 + kc) * 32 + lane);
                uint4 bq = *(const uint4*)&Kp4[bi * 4];   // [kh0,kh1,kl0,kl1]
                float* c = sreg[nt];
                mma_bf16(c[0], c[1], c[2], c[3], ah.x, ah.y, ah.z, ah.w, bq.x, bq.y);
                mma_bf16(c[0], c[1], c[2], c[3], ah.x, ah.y, ah.z, ah.w, bq.z, bq.w);
                mma_bf16(c[0], c[1], c[2], c[3], al.x, al.y, al.z, al.w, bq.x, bq.y);
            }
        }

        float mx0 = m0, mx1 = m1;
#pragma unroll
        for (int nt = 0; nt < 8; ++nt) {
            int tb = t0 + (nt << 3) + ((lane & 3) << 1);
            if (tb > qg)     sreg[nt][0] = -1e30f;
            if (tb + 1 > qg) sreg[nt][1] = -1e30f;
            if (tb > qg + 8)     sreg[nt][2] = -1e30f;
            if (tb + 1 > qg + 8) sreg[nt][3] = -1e30f;
            mx0 = fmaxf(mx0, fmaxf(sreg[nt][0], sreg[nt][1]));
            mx1 = fmaxf(mx1, fmaxf(sreg[nt][2], sreg[nt][3]));
        }
        mx0 = fmaxf(mx0, __shfl_xor_sync(0xffffffffu, mx0, 1));
        mx0 = fmaxf(mx0, __shfl_xor_sync(0xffffffffu, mx0, 2));
        mx1 = fmaxf(mx1, __shfl_xor_sync(0xffffffffu, mx1, 1));
        mx1 = fmaxf(mx1, __shfl_xor_sync(0xffffffffu, mx1, 2));
        float corr0 = exp2p(m0 - mx0), corr1 = exp2p(m1 - mx1);
        m0 = mx0; m1 = mx1;
        l0s *= corr0; l1s *= corr1;
#pragma unroll
        for (int nt = 0; nt < 8; ++nt) {
            o[nt][0] *= corr0; o[nt][1] *= corr0;
            o[nt][2] *= corr1; o[nt][3] *= corr1;
        }
        float ls0 = 0.f, ls1 = 0.f;
#pragma unroll
        for (int nt = 0; nt < 8; ++nt) {
            float p0 = exp2p(sreg[nt][0] - mx0);
            float p1 = exp2p(sreg[nt][1] - mx0);
            float p2 = exp2p(sreg[nt][2] - mx1);
            float p3 = exp2p(sreg[nt][3] - mx1);
            sreg[nt][0] = p0; sreg[nt][1] = p1;
            sreg[nt][2] = p2; sreg[nt][3] = p3;
            ls0 += p0 + p1; ls1 += p2 + p3;
        }
        ls0 += __shfl_xor_sync(0xffffffffu, ls0, 1);
        ls0 += __shfl_xor_sync(0xffffffffu, ls0, 2);
        ls1 += __shfl_xor_sync(0xffffffffu, ls1, 1);
        ls1 += __shfl_xor_sync(0xffffffffu, ls1, 2);
        l0s += ls0; l1s += ls1;

#pragma unroll
        for (int j = 0; j < 4; ++j) {
            float* pA = sreg[2 * j];
            float* pB = sreg[2 * j + 1];
            unsigned ah0 = bf2pack(pA[0], pA[1]);
            unsigned ah1 = bf2pack(pA[2], pA[3]);
            unsigned ah2 = bf2pack(pB[0], pB[1]);
            unsigned ah3 = bf2pack(pB[2], pB[3]);
            unsigned al0 = bf2pack(pA[0] - bfhi(pA[0]), pA[1] - bfhi(pA[1]));
            unsigned al1 = bf2pack(pA[2] - bfhi(pA[2]), pA[3] - bfhi(pA[3]));
            unsigned al2 = bf2pack(pB[0] - bfhi(pB[0]), pB[1] - bfhi(pB[1]));
            unsigned al3 = bf2pack(pB[2] - bfhi(pB[2]), pB[3] - bfhi(pB[3]));
#pragma unroll
            for (int nt = 0; nt < 8; ++nt) {
                int bi = ((nt * 4 + j) * 32 + lane);
                uint4 vq = *(const uint4*)&Vp4[bi * 4];   // [vh0,vh1,vl0,vl1]
                float* c = o[nt];
                mma_bf16(c[0], c[1], c[2], c[3], ah0, ah1, ah2, ah3, vq.x, vq.y);
                mma_bf16(c[0], c[1], c[2], c[3], ah0, ah1, ah2, ah3, vq.z, vq.w);
                mma_bf16(c[0], c[1], c[2], c[3], al0, al1, al2, al3, vq.x, vq.y);
            }
        }
    }

    const float inv0 = 1.f / l0s, inv1 = 1.f / l1s;
    float* Op = O + base;
#pragma unroll
    for (int nt = 0; nt < 8; ++nt) {
        int d = (nt << 3) + ((lane & 3) << 1);
        Op[(size_t)d * SS + qg]       = o[nt][0] * inv0;
        Op[(size_t)(d + 1) * SS + qg] = o[nt][1] * inv0;
        Op[(size_t)d * SS + qg + 8]       = o[nt][2] * inv1;
        Op[(size_t)(d + 1) * SS + qg + 8] = o[nt][3] * inv1;
    }
}

// ---------------------------------------------------------------------------
// combined = attn_l - lam*attn_r; LayerNorm over E; lambda inline (warp 0).
// 1024 threads = 32 e-groups x 32 s; grid = B*S/32 = 128.
// ---------------------------------------------------------------------------
__global__ __launch_bounds__(1024) void ln_kernel(
    const float* __restrict__ al, const float* __restrict__ ar,
    const float* __restrict__ gg, const float* __restrict__ bbv,
    const float* __restrict__ lql, const float* __restrict__ lkl,
    const float* __restrict__ lqr, const float* __restrict__ lkr,
    float* __restrict__ out)
{
    __shared__ float ps[32][32], pq[32][32], smu[32], srs[32], slam;
    const int tid = threadIdx.x;
    const int ty = tid >> 5, sl = tid & 31;

    if (tid < 32) {
        float a = lql[tid] * lkl[tid] + lql[tid + 32] * lkl[tid + 32];
        float b = lqr[tid] * lkr[tid] + lqr[tid + 32] * lkr[tid + 32];
#pragma unroll
        for (int off = 16; off > 0; off >>= 1) {
            a += __shfl_xor_sync(0xffffffffu, a, off);
            b += __shfl_xor_sync(0xffffffffu, b, off);
        }
        if (tid == 0) slam = expf(a) - expf(b) + 0.1f;
    }
    __syncthreads();
    const float lam = slam;

    const int b = blockIdx.x >> 6;
    const int s = ((blockIdx.x & 63) << 5) + sl;
    const size_t col = (size_t)b * EE * SS + s;
    const int e0 = ty << 5;

    float sum = 0.f, sq = 0.f;
    for (int e = e0; e < e0 + 32; ++e) {
        size_t idx = col + (size_t)e * SS;
        float c = al[idx] - lam * ar[idx];
        sum += c; sq += c * c;
    }
    ps[ty][sl] = sum; pq[ty][sl] = sq;
    __syncthreads();
    if (ty == 0) {
        float ts = 0.f, tq = 0.f;
#pragma unroll
        for (int r = 0; r < 32; ++r) { ts += ps[r][sl]; tq += pq[r][sl]; }
        float mu = ts * (1.f / EE);
        float var = tq * (1.f / EE) - mu * mu;
        smu[sl] = mu;
        srs[sl] = rsqrtf(var + 1e-5f);
    }
    __syncthreads();
    const float mu = smu[sl], rs = srs[sl];
    for (int e = e0; e < e0 + 32; ++e) {
        size_t idx = col + (size_t)e * SS;
        float c = al[idx] - lam * ar[idx];
        out[idx] = (c - mu) * rs * gg[e] + bbv[e];
    }
}

// ---------------------------------------------------------------------------
// Launch
// ---------------------------------------------------------------------------
static float* sym_addr(const void* symbol)
{
    void* p = nullptr;
    cudaGetSymbolAddress(&p, symbol);
    return (float*)p;
}

extern "C" void kernel_launch(void* const* d_in, const int* in_sizes, int n_in,
                              void* d_out, int out_size)
{
    const float* left  = (const float*)d_in[0];
    const float* right = (const float*)d_in[1];
    const float* Wq_l  = (const float*)d_in[2];
    const float* Wk_l  = (const float*)d_in[3];
    const float* Wv_l  = (const float*)d_in[4];
    const float* Wq_r  = (const float*)d_in[5];
    const float* Wk_r  = (const float*)d_in[6];
    const float* Wv_r  = (const float*)d_in[7];
    const float* Wo    = (const float*)d_in[8];
    const float* lql   = (const float*)d_in[9];
    const float* lkl   = (const float*)d_in[10];
    const float* lqr   = (const float*)d_in[11];
    const float* lkr   = (const float*)d_in[12];
    const float* ln_g  = (const float*)d_in[13];
    const float* ln_b  = (const float*)d_in[14];
    const float* W1    = (const float*)d_in[15];
    const float* b1    = (const float*)d_in[16];
    const float* W2    = (const float*)d_in[17];
    const float* b2    = (const float*)d_in[18];
    float* out = (float*)d_out;

    float* ql = sym_addr(g_ql); float* kl = sym_addr(g_kl); float* vl = sym_addr(g_vl);
    float* qr = sym_addr(g_qr); float* kr = sym_addr(g_kr); float* vr = sym_addr(g_vr);
    float* al = sym_addr(g_al); float* ar = sym_addr(g_ar);
    float* lno = sym_addr(g_lnout);
    float* h1 = sym_addr(g_h1);
    float* wf = sym_addr(g_wf);

    // D^-0.5 * log2(e): scores in log2 domain (softmax-invariant)
    const float qscale = 0.125f * 1.4426950408889634f;

    cudaFuncSetAttribute(gemm_tc, cudaFuncAttributeMaxDynamicSharedMemorySize,
                         GEMM_SMEM);
    cudaFuncSetAttribute(gemm_qkvwf, cudaFuncAttributeMaxDynamicSharedMemorySize,
                         GEMM_SMEM);
    cudaFuncSetAttribute(attn_mma, cudaFuncAttributeMaxDynamicSharedMemorySize,
                         ATTN_SMEM);

    dim3 blk(256);

    // QKV projections + Wf=W1@Wo fused into one launch (z = 0..12)
    gemm_qkvwf<<<dim3(SS / 128, EE / 128, 13), blk, GEMM_SMEM>>>(
        Wq_l, Wk_l, Wv_l, Wq_r, Wk_r, Wv_r, left, right, W1, Wo, wf,
        ql, kl, vl, qr, kr, vr, qscale);

    // attention: both paths in one launch (z = path*2 + b)
    attn_mma<<<dim3(SS / 128, HH, 2 * BB), 256, ATTN_SMEM>>>(
        ql, kl, vl, al, qr, kr, vr, ar);

    // combine + LN (lambda computed inline)
    ln_kernel<<<BB * (SS / 32), 1024>>>(al, ar, ln_g, ln_b,
                                        lql, lkl, lqr, lkr, lno);

    // fused (W1@Wo) + relu, then W2 straight into d_out ([B,E,S])
    gemm_tc<<<dim3(SS / 128, 2 * EE / 128, BB), blk, GEMM_SMEM>>>(
        wf, lno, h1, 2 * EE, EE, SS, b1, 1.f, 1);
    gemm_tc<<<dim3(SS / 128, EE / 128, BB), blk, GEMM_SMEM>>>(
        W2, h1, out, EE, 2 * EE, SS, b2, 1.f, 0);
}